// round 14
// baseline (speedup 1.0000x reference)
#include <cuda_runtime.h>
#include <cuda_bf16.h>
#include <cstdint>

// ===========================================================================
// Causal self-attention via mma.sync bf16 (sm_103 non-'a' compatible).
// All GEMMs: bf16 3-term hi/lo split (fp32-accurate), fp32 accumulate.
// GEMM: CTA tile 128x128, 4 warps (warp tile 64x64), BK=64, 3-stage cp.async
//       (staged mid-chunk), 2 CTAs/SM (register-bound).
// Schedule (best measured): convW on s2 under convX (legal fork via eFork0);
// projQ main / projK s1 / projV+V^T s2; scoresA(odd)->smA->PVA on main,
// scoresB(even)->smB->PVB chained on s1 after scoresA (eSA).
// ===========================================================================

namespace cfg {
constexpr int B = 4;
constexpr int S = 2048;
constexpr int D = 1024;
constexpr int MR = B * S;          // 8192
}

// ---------------- scratch (__device__ globals; no allocations) -------------
__device__ float g_v[cfg::MR * cfg::D];
__device__ float g_p[(long long)cfg::B * cfg::S * cfg::S];

// bf16 hi/lo planes, stored as [rows][2K] = [hi(0..K-1) | lo(0..K-1)]
__device__ unsigned short g_x2 [(long long)cfg::MR * 2 * cfg::D];
__device__ unsigned short g_wq2[(long long)cfg::D  * 2 * cfg::D];   // [n][2K], W^T
__device__ unsigned short g_wk2[(long long)cfg::D  * 2 * cfg::D];
__device__ unsigned short g_wv2[(long long)cfg::D  * 2 * cfg::D];
__device__ unsigned short g_q2 [(long long)cfg::MR * 2 * cfg::D];
__device__ unsigned short g_k2 [(long long)cfg::MR * 2 * cfg::D];
__device__ unsigned short g_v2t[(long long)cfg::B * cfg::D * 2 * cfg::S]; // [b][d][2S], V^T
__device__ unsigned short g_p2 [(long long)cfg::B * cfg::S * 2 * cfg::S];

// ---------------- PTX helpers ----------------------------------------------
__device__ __forceinline__ uint32_t smem_u32(const void* p) {
    uint32_t a;
    asm("{ .reg .u64 t; cvta.to.shared.u64 t, %1; cvt.u32.u64 %0, t; }"
        : "=r"(a) : "l"(p));
    return a;
}

#define CP_ASYNC_16(dst, src)                                                 \
    asm volatile("cp.async.cg.shared.global [%0], [%1], 16;"                  \
                 :: "r"(dst), "l"(src))
#define CP_COMMIT() asm volatile("cp.async.commit_group;" ::: "memory")
#define CP_WAIT_1() asm volatile("cp.async.wait_group 1;" ::: "memory")
#define CP_WAIT_0() asm volatile("cp.async.wait_group 0;" ::: "memory")

#define LDSM_X4(r0, r1, r2, r3, addr)                                         \
    asm volatile("ldmatrix.sync.aligned.m8n8.x4.shared.b16 {%0,%1,%2,%3}, [%4];" \
                 : "=r"(r0), "=r"(r1), "=r"(r2), "=r"(r3) : "r"(addr))

#define MMA_BF16(d, a, b)                                                     \
    asm volatile("mma.sync.aligned.m16n8k16.row.col.f32.bf16.bf16.f32 "       \
                 "{%0,%1,%2,%3},{%4,%5,%6,%7},{%8,%9},{%0,%1,%2,%3};"         \
                 : "+f"((d)[0]), "+f"((d)[1]), "+f"((d)[2]), "+f"((d)[3])     \
                 : "r"((a)[0]), "r"((a)[1]), "r"((a)[2]), "r"((a)[3]),        \
                   "r"((b)[0]), "r"((b)[1]))

// ---------------- hi/lo split helper ---------------------------------------
__device__ __forceinline__ void split1(float v, unsigned short& h, unsigned short& l) {
    __nv_bfloat16 hb = __float2bfloat16(v);
    float rem = v - __bfloat162float(hb);
    __nv_bfloat16 lb = __float2bfloat16(rem);
    h = __bfloat16_as_ushort(hb);
    l = __bfloat16_as_ushort(lb);
}

// fp32 [rows][K] -> bf16 [rows][2K] (hi plane | lo plane)
__global__ __launch_bounds__(256) void conv_split(
    const float* __restrict__ in, unsigned short* __restrict__ out,
    unsigned int total4, unsigned int Kq /* = K/4 */, int K)
{
    for (unsigned int i = blockIdx.x * blockDim.x + threadIdx.x; i < total4;
         i += gridDim.x * blockDim.x) {
        unsigned int r = i / Kq;
        unsigned int c4 = i - r * Kq;
        float4 v = *(const float4*)(in + (long long)r * K + c4 * 4);
        unsigned short h0, h1, h2, h3, l0, l1, l2, l3;
        split1(v.x, h0, l0); split1(v.y, h1, l1);
        split1(v.z, h2, l2); split1(v.w, h3, l3);
        uint2 hv, lv;
        hv.x = (uint32_t)h0 | ((uint32_t)h1 << 16);
        hv.y = (uint32_t)h2 | ((uint32_t)h3 << 16);
        lv.x = (uint32_t)l0 | ((uint32_t)l1 << 16);
        lv.y = (uint32_t)l2 | ((uint32_t)l3 << 16);
        unsigned short* orow = out + (long long)r * 2 * K;
        *(uint2*)(orow + c4 * 4)     = hv;
        *(uint2*)(orow + K + c4 * 4) = lv;
    }
}

// fp32 [Krows][Ncols] -> bf16 [Ncols][2*Krows] transposed hi/lo (for W^T, V^T)
// zmode=1: blockIdx.z selects tensor (weights fused); zmode=0: z is batch.
__global__ __launch_bounds__(256) void conv_split_T(
    const float* __restrict__ in0, const float* __restrict__ in1,
    const float* __restrict__ in2,
    unsigned short* __restrict__ out0, unsigned short* __restrict__ out1,
    unsigned short* __restrict__ out2,
    int Krows, int Ncols, long long sIn, long long sOut, int zmode)
{
    __shared__ float t[32][33];
    const float* ib;
    unsigned short* ob;
    if (zmode) {
        ib = (blockIdx.z == 0) ? in0 : (blockIdx.z == 1) ? in1 : in2;
        ob = (blockIdx.z == 0) ? out0 : (blockIdx.z == 1) ? out1 : out2;
    } else {
        ib = in0 + (long long)blockIdx.z * sIn;
        ob = out0 + (long long)blockIdx.z * sOut;
    }
    const int k0 = blockIdx.y * 32, n0 = blockIdx.x * 32;
    const int tx = threadIdx.x, ty = threadIdx.y;     // (32, 8)
#pragma unroll
    for (int i = 0; i < 4; i++)
        t[ty + i * 8][tx] = ib[(long long)(k0 + ty + i * 8) * Ncols + n0 + tx];
    __syncthreads();
    const int ld2 = 2 * Krows;
#pragma unroll
    for (int i = 0; i < 4; i++) {
        int n = n0 + ty + i * 8;
        int k = k0 + tx;
        unsigned short h, l;
        split1(t[tx][ty + i * 8], h, l);
        ob[(long long)n * ld2 + k]         = h;
        ob[(long long)n * ld2 + Krows + k] = l;
    }
}

// ===========================================================================
// mma.sync GEMM: C[m,n] = sum over 3 bf16 term-pairs of A2,B2 (+bias)
//   A2: [M][2K] hi|lo, segments {hi,hi,lo};  B2: [N][2K] hi|lo, segs {hi,lo,hi}
// CTA tile 128x128, 4 warps, warp tile 64x64 (2x2 grid), BK=64, 3-stage,
// next-next chunk staged mid-chunk.
// TRI: triangular-packed grid — blockIdx.x enumerates lower-triangle tiles
//      of parity yBase (rows mIdx = 2j+yBase, j=0..7; cum_j = j*(j+yBase)).
// Otherwise: m-tile = yIdx*yStride + yBase; KBOUND reverses y (longest first).
// EPI_SPLIT: C is ushort* [M][2N] hi|lo (fused output split for Q/K).
// ===========================================================================
template <bool HAS_BIAS, bool TRI, bool KBOUND, bool EPI_SPLIT>
__global__ __launch_bounds__(128, 2) void mma_gemm(
    const unsigned short* __restrict__ A2, const unsigned short* __restrict__ B2,
    const float* __restrict__ bias, void* __restrict__ Cv,
    int Ndim, int Kdim, long long sA, long long sB, long long sC,
    int yStride, int yBase)
{
    int m0, n0;
    if (TRI) {
        const int t = blockIdx.x;
        int j = 0;
#pragma unroll
        for (int jj = 1; jj < 8; jj++)
            if (jj * (jj + yBase) <= t) j = jj;
        const int n = t - j * (j + yBase);
        m0 = (2 * j + yBase) * 128;
        n0 = n * 128;
    } else {
        const int yIdx = KBOUND ? (gridDim.y - 1 - blockIdx.y) : blockIdx.y;
        m0 = (yIdx * yStride + yBase) * 128;
        n0 = blockIdx.x * 128;
    }

    extern __shared__ char dynsmem[];
    const uint32_t sb = smem_u32(dynsmem);

    const int tid  = threadIdx.x;
    const int lane = tid & 31;
    const int warp = tid >> 5;
    const int wm   = warp >> 1;       // 0..1
    const int wn   = warp & 1;        // 0..1

    const long long ldAe = 2LL * Kdim;            // elements per row
    const long long ldBytes = ldAe * 2;
    const char* baseA = (const char*)(A2 + (long long)blockIdx.z * sA + (long long)m0 * ldAe);
    const char* baseB = (const char*)(B2 + (long long)blockIdx.z * sB + (long long)n0 * ldAe);

    const int segK = KBOUND ? (m0 + 128) : Kdim;
    const int nps = segK >> 6;                    // 64-elem chunks per segment
    const int nChunks = 3 * nps;

    // ---- staging mapping: 128 threads; thread -> (row, 16B unit)
    const int srow = tid >> 3;                    // 0..15
    const int su   = tid & 7;                     // 0..7
    const uint32_t sdst = (uint32_t)(srow * 128 + ((su ^ (srow & 7)) << 4));
    const long long sgoff = (long long)srow * ldBytes + su * 16;

    auto stage = [&](int c, int buf) {
        const int seg = c / nps, kc = c - seg * nps;
        const long long offA = ((long long)kc * 64 + (seg == 2 ? (long long)Kdim : 0)) * 2;
        const long long offB = ((long long)kc * 64 + (seg == 1 ? (long long)Kdim : 0)) * 2;
        const char* ga = baseA + offA + sgoff;
        const char* gb = baseB + offB + sgoff;
        const uint32_t da = sb + buf * 32768u + sdst;
        const uint32_t db = da + 16384u;
#pragma unroll
        for (int i = 0; i < 8; i++) {     // 128 rows each, 16 apart
            CP_ASYNC_16(da + i * 2048u, ga + (long long)i * 16 * ldBytes);
            CP_ASYNC_16(db + i * 2048u, gb + (long long)i * 16 * ldBytes);
        }
        CP_COMMIT();
    };

    float acc[4][8][4];
#pragma unroll
    for (int i = 0; i < 4; i++)
#pragma unroll
        for (int j2 = 0; j2 < 8; j2++)
#pragma unroll
            for (int t2 = 0; t2 < 4; t2++) acc[i][j2][t2] = 0.f;

    // per-lane ldmatrix address components (XOR swizzle: chunk ^= row&7)
    const uint32_t aRowBase = (uint32_t)(wm * 64 + (lane & 15));
    const uint32_t aChunkX  = (uint32_t)(lane >> 4);
    const uint32_t bRowBase = (uint32_t)(wn * 64 + (lane & 7) + ((lane & 16) >> 1));
    const uint32_t bChunkX  = (uint32_t)((lane >> 3) & 1);
    const uint32_t lxor     = (uint32_t)(lane & 7);

    stage(0, 0);
    stage(1, 1);

    for (int c = 0; c < nChunks; c++) {
        if (c + 1 < nChunks) { CP_WAIT_1(); } else { CP_WAIT_0(); }
        __syncthreads();

        const uint32_t sAb = sb + (uint32_t)(c % 3) * 32768u;
        const uint32_t sBb = sAb + 16384u;

        auto compute_s = [&](int s) {
            uint32_t a[4][4];
            uint32_t b[4][4];          // [nb2][{b0lo,b0hi,b1lo,b1hi}]
#pragma unroll
            for (int mb = 0; mb < 4; mb++) {
                const uint32_t addr = sAb + (aRowBase + mb * 16) * 128u
                                    + (((s * 2 + aChunkX) ^ lxor) << 4);
                LDSM_X4(a[mb][0], a[mb][1], a[mb][2], a[mb][3], addr);
            }
#pragma unroll
            for (int nb2 = 0; nb2 < 4; nb2++) {
                const uint32_t addr = sBb + (bRowBase + nb2 * 16) * 128u
                                    + (((s * 2 + bChunkX) ^ lxor) << 4);
                LDSM_X4(b[nb2][0], b[nb2][1], b[nb2][2], b[nb2][3], addr);
            }
#pragma unroll
            for (int nb2 = 0; nb2 < 4; nb2++)
#pragma unroll
                for (int mb = 0; mb < 4; mb++) {
                    MMA_BF16(acc[mb][nb2 * 2],     a[mb], &b[nb2][0]);
                    MMA_BF16(acc[mb][nb2 * 2 + 1], a[mb], &b[nb2][2]);
                }
        };

        compute_s(0);
        compute_s(1);
        if (c + 2 < nChunks) stage(c + 2, (c + 2) % 3);  // mid-chunk prefetch
        compute_s(2);
        compute_s(3);
    }

    // ---- epilogue ----------------------------------------------------------
    const int rBase = m0 + wm * 64 + (lane >> 2);
    const int cBase = n0 + wn * 64 + (lane & 3) * 2;

    if (EPI_SPLIT) {
        unsigned short* Cs = (unsigned short*)Cv + (long long)blockIdx.z * sC;
#pragma unroll
        for (int nb = 0; nb < 8; nb++) {
            const int cc = cBase + nb * 8;
            float bx = 0.f, by = 0.f;
            if (HAS_BIAS) { bx = bias[cc]; by = bias[cc + 1]; }
#pragma unroll
            for (int mb = 0; mb < 4; mb++) {
                const int r = rBase + mb * 16;
#pragma unroll
                for (int half = 0; half < 2; half++) {
                    const float v0 = acc[mb][nb][half * 2]     + bx;
                    const float v1 = acc[mb][nb][half * 2 + 1] + by;
                    unsigned short h0, l0, h1, l1;
                    split1(v0, h0, l0);
                    split1(v1, h1, l1);
                    unsigned short* row = Cs + (long long)(r + half * 8) * (2 * Ndim);
                    *(uint32_t*)(row + cc)        = (uint32_t)h0 | ((uint32_t)h1 << 16);
                    *(uint32_t*)(row + Ndim + cc) = (uint32_t)l0 | ((uint32_t)l1 << 16);
                }
            }
        }
    } else {
        float* Cb = (float*)Cv + (long long)blockIdx.z * sC;
#pragma unroll
        for (int nb = 0; nb < 8; nb++) {
            const int cc = cBase + nb * 8;
            float bx = 0.f, by = 0.f;
            if (HAS_BIAS) { bx = bias[cc]; by = bias[cc + 1]; }
#pragma unroll
            for (int mb = 0; mb < 4; mb++) {
                const int r = rBase + mb * 16;
                float2 v0, v1;
                v0.x = acc[mb][nb][0] + bx; v0.y = acc[mb][nb][1] + by;
                v1.x = acc[mb][nb][2] + bx; v1.y = acc[mb][nb][3] + by;
                *(float2*)(Cb + (long long)r * Ndim + cc)       = v0;
                *(float2*)(Cb + (long long)(r + 8) * Ndim + cc) = v1;
            }
        }
    }
}

// ===========================================================================
// Register-resident causal softmax, emits bf16 hi/lo split planes directly.
// parity selects which 128-row tiles this launch handles (q/128 parity).
// Grid = B * S/2 blocks. Loads only [0, blockEnd) of the row.
// ===========================================================================
__global__ __launch_bounds__(256) void softmax_split(
    const float* __restrict__ P, unsigned short* __restrict__ P2, int parity)
{
    using namespace cfg;
    const int idx = blockIdx.x;              // 0 .. B*S/2-1
    const int b   = idx >> 10;               // S/2 = 1024 rows per batch half
    const int r   = idx & 1023;
    const int q   = (((r >> 7) << 1) + parity) * 128 + (r & 127);
    const float* src = P + (long long)b * S * S + (long long)q * S;
    unsigned short* dst = P2 + ((long long)b * S + q) * (2 * S);
    const int len = q + 1;
    const int blockEnd = ((q >> 7) + 1) << 7;
    const int tid = threadIdx.x;

    __shared__ float red[256];

    float v[8];
#pragma unroll
    for (int j = 0; j < 2; j++) {
        const int i0 = (tid + j * 256) * 4;
        if (i0 < blockEnd) {
            *(float4*)&v[j * 4] = *(const float4*)(src + i0);
        } else {
            v[j * 4] = v[j * 4 + 1] = v[j * 4 + 2] = v[j * 4 + 3] = 0.f;
        }
    }

    float m = -3.4e38f;
#pragma unroll
    for (int j = 0; j < 2; j++)
#pragma unroll
        for (int t = 0; t < 4; t++) {
            const int i = (tid + j * 256) * 4 + t;
            if (i < len) m = fmaxf(m, v[j * 4 + t]);
        }
    red[tid] = m;
    __syncthreads();
#pragma unroll
    for (int s2 = 128; s2 > 0; s2 >>= 1) {
        if (tid < s2) red[tid] = fmaxf(red[tid], red[tid + s2]);
        __syncthreads();
    }
    m = red[0];
    __syncthreads();

    float e[8];
    float sum = 0.f;
#pragma unroll
    for (int j = 0; j < 2; j++)
#pragma unroll
        for (int t = 0; t < 4; t++) {
            const int i = (tid + j * 256) * 4 + t;
            const float ev = (i < len) ? __expf(v[j * 4 + t] - m) : 0.f;
            e[j * 4 + t] = ev;
            sum += ev;
        }
    red[tid] = sum;
    __syncthreads();
#pragma unroll
    for (int s2 = 128; s2 > 0; s2 >>= 1) {
        if (tid < s2) red[tid] += red[tid + s2];
        __syncthreads();
    }
    const float inv = 1.f / red[0];

#pragma unroll
    for (int j = 0; j < 2; j++) {
        const int i = (tid + j * 256) * 4;
        if (i < blockEnd) {
            unsigned short h[4], l[4];
#pragma unroll
            for (int t = 0; t < 4; t++) split1(e[j * 4 + t] * inv, h[t], l[t]);
            uint2 hv, lv;
            hv.x = (uint32_t)h[0] | ((uint32_t)h[1] << 16);
            hv.y = (uint32_t)h[2] | ((uint32_t)h[3] << 16);
            lv.x = (uint32_t)l[0] | ((uint32_t)l[1] << 16);
            lv.y = (uint32_t)l[2] | ((uint32_t)l[3] << 16);
            *(uint2*)(dst + i)     = hv;
            *(uint2*)(dst + S + i) = lv;
        }
    }
}

// ---------------- persistent stream/event pool (lazy, one-time) ------------
struct StreamPool {
    cudaStream_t s1, s2;
    cudaEvent_t eFork0, eW, eFork, eK, eV, eSA, eJ;
    StreamPool() {
        cudaStreamCreateWithFlags(&s1, cudaStreamNonBlocking);
        cudaStreamCreateWithFlags(&s2, cudaStreamNonBlocking);
        cudaEventCreateWithFlags(&eFork0, cudaEventDisableTiming);
        cudaEventCreateWithFlags(&eW,     cudaEventDisableTiming);
        cudaEventCreateWithFlags(&eFork,  cudaEventDisableTiming);
        cudaEventCreateWithFlags(&eK,     cudaEventDisableTiming);
        cudaEventCreateWithFlags(&eV,     cudaEventDisableTiming);
        cudaEventCreateWithFlags(&eSA,    cudaEventDisableTiming);
        cudaEventCreateWithFlags(&eJ,     cudaEventDisableTiming);
    }
};
static StreamPool& pool() { static StreamPool p; return p; }

// ===========================================================================
// launch — forked-stream capture (best-measured R12 topology + convW overlap):
//   main: [eFork0] convX -> [wait eW] -> projQ -> scoresA(odd,tri) -> smA -> PVA
//   s2:   [wait eFork0] convW [eW] ; (post-fork) projV -> conv V^T [eV]
//   s1:   projK [eK] ; [wait eSA] scoresB(even,tri) -> smB -> [wait eV] PVB
// ===========================================================================
extern "C" void kernel_launch(void* const* d_in, const int* in_sizes, int n_in,
                              void* d_out, int out_size)
{
    using namespace cfg;
    const float* x  = (const float*)d_in[0];
    const float* Wq = (const float*)d_in[1];
    const float* bq = (const float*)d_in[2];
    const float* Wk = (const float*)d_in[3];
    const float* bk = (const float*)d_in[4];
    const float* Wv = (const float*)d_in[5];
    const float* bv = (const float*)d_in[6];
    float* out = (float*)d_out;

    float *v, *p;
    unsigned short *x2, *wq2, *wk2, *wv2, *q2, *k2, *v2t, *p2;
    cudaGetSymbolAddress((void**)&v, g_v);
    cudaGetSymbolAddress((void**)&p, g_p);
    cudaGetSymbolAddress((void**)&x2,  g_x2);
    cudaGetSymbolAddress((void**)&wq2, g_wq2);
    cudaGetSymbolAddress((void**)&wk2, g_wk2);
    cudaGetSymbolAddress((void**)&wv2, g_wv2);
    cudaGetSymbolAddress((void**)&q2,  g_q2);
    cudaGetSymbolAddress((void**)&k2,  g_k2);
    cudaGetSymbolAddress((void**)&v2t, g_v2t);
    cudaGetSymbolAddress((void**)&p2,  g_p2);

    const int SMEM_DYN = 98304;   // 3 stages x (16KB A + 16KB B)
    cudaFuncSetAttribute(mma_gemm<true,  false, false, true>,
                         cudaFuncAttributeMaxDynamicSharedMemorySize, SMEM_DYN);
    cudaFuncSetAttribute(mma_gemm<true,  false, false, false>,
                         cudaFuncAttributeMaxDynamicSharedMemorySize, SMEM_DYN);
    cudaFuncSetAttribute(mma_gemm<false, true,  false, false>,
                         cudaFuncAttributeMaxDynamicSharedMemorySize, SMEM_DYN);
    cudaFuncSetAttribute(mma_gemm<false, false, true,  false>,
                         cudaFuncAttributeMaxDynamicSharedMemorySize, SMEM_DYN);

    StreamPool& sp = pool();   // created on first (correctness) call only

    // ---- fork s2 immediately; convW runs there under convX ----------------
    cudaEventRecord(sp.eFork0, 0);
    cudaStreamWaitEvent(sp.s2, sp.eFork0, 0);
    {
        dim3 g(D / 32, D / 32, 3), b2(32, 8);
        conv_split_T<<<g, b2, 0, sp.s2>>>(Wq, Wk, Wv, wq2, wk2, wv2, D, D, 0, 0, 1);
    }
    cudaEventRecord(sp.eW, sp.s2);

    // ---- main: x split ----------------------------------------------------
    conv_split<<<8192, 256>>>(x, x2, (unsigned)(MR * D / 4), (unsigned)(D / 4), D);
    cudaStreamWaitEvent(0, sp.eW, 0);
    cudaEventRecord(sp.eFork, 0);
    cudaStreamWaitEvent(sp.s1, sp.eFork, 0);
    cudaStreamWaitEvent(sp.s2, sp.eFork, 0);

    // ---- projections: Q main, K on s1, V (+transpose) on s2 -------------
    {
        dim3 g(D / 128, MR / 128, 1), b2(128);
        mma_gemm<true, false, false, true ><<<g, b2, SMEM_DYN, 0    >>>(x2, wq2, bq, q2, D, D, 0, 0, 0, 1, 0);
        mma_gemm<true, false, false, true ><<<g, b2, SMEM_DYN, sp.s1>>>(x2, wk2, bk, k2, D, D, 0, 0, 0, 1, 0);
        mma_gemm<true, false, false, false><<<g, b2, SMEM_DYN, sp.s2>>>(x2, wv2, bv, v,  D, D, 0, 0, 0, 1, 0);
    }
    {   // V^T hi/lo per batch, stays on s2
        dim3 g(D / 32, S / 32, B), b2(32, 8);
        conv_split_T<<<g, b2, 0, sp.s2>>>(v, nullptr, nullptr, v2t, nullptr, nullptr,
                                          S, D, (long long)S * D, (long long)D * 2 * S, 0);
    }
    cudaEventRecord(sp.eK, sp.s1);
    cudaEventRecord(sp.eV, sp.s2);

    const long long sAsc = (long long)S * 2 * D, sCsc = (long long)S * S;
    const long long sApv = (long long)S * 2 * S, sBpv = (long long)D * 2 * S;
    const long long sCpv = (long long)S * D;

    // ---- scoresA (odd m-tiles, triangular grid) on main -------------------
    cudaStreamWaitEvent(0, sp.eK, 0);
    {
        dim3 g(72, 1, B), b2(128);   // parity 1: sum_{j=0..7}(2j+2) = 72 tiles
        mma_gemm<false, true, false, false><<<g, b2, SMEM_DYN>>>(
            q2, k2, nullptr, p, S, D, sAsc, sAsc, sCsc, 0, 1);
    }
    cudaEventRecord(sp.eSA, 0);

    // ---- s1: scoresB (even, triangular) -> softmaxB -> PVB ----------------
    cudaStreamWaitEvent(sp.s1, sp.eSA, 0);
    {
        dim3 g(64, 1, B), b2(128);   // parity 0: sum_{j=0..7}(2j+1) = 64 tiles
        mma_gemm<false, true, false, false><<<g, b2, SMEM_DYN, sp.s1>>>(
            q2, k2, nullptr, p, S, D, sAsc, sAsc, sCsc, 0, 0);
    }
    softmax_split<<<B * S / 2, 256, 0, sp.s1>>>(p, p2, 0);
    cudaStreamWaitEvent(sp.s1, sp.eV, 0);
    {
        dim3 g(D / 128, 8, B), b2(128);
        mma_gemm<false, false, true, false><<<g, b2, SMEM_DYN, sp.s1>>>(
            p2, v2t, nullptr, out, D, S, sApv, sBpv, sCpv, 2, 0);
    }
    cudaEventRecord(sp.eJ, sp.s1);

    // ---- main: softmaxA (odd) -> PVA (odd) --------------------------------
    softmax_split<<<B * S / 2, 256>>>(p, p2, 1);
    cudaStreamWaitEvent(0, sp.eV, 0);
    {
        dim3 g(D / 128, 8, B), b2(128);
        mma_gemm<false, false, true, false><<<g, b2, SMEM_DYN>>>(
            p2, v2t, nullptr, out, D, S, sApv, sBpv, sCpv, 2, 1);
    }
    cudaStreamWaitEvent(0, sp.eJ, 0);   // join s1 back into main
}

// round 15
// speedup vs baseline: 1.0513x; 1.0513x over previous
#include <cuda_runtime.h>
#include <cuda_bf16.h>
#include <cstdint>

// ===========================================================================
// Causal self-attention via mma.sync bf16 (sm_103 non-'a' compatible).
// All GEMMs: bf16 3-term hi/lo split (fp32-accurate), fp32 accumulate.
// GEMM: CTA tile 128x128, 4 warps (warp tile 64x64), BK=64, 3-stage cp.async
//       (staged mid-chunk), 2 CTAs/SM.
// Schedule (best measured, R10): parity-split scores/softmax/PV pipelines on
// two streams; K-proj on s1, V-proj+V^T on s2; convX/convW serial pre-fork.
// ===========================================================================

namespace cfg {
constexpr int B = 4;
constexpr int S = 2048;
constexpr int D = 1024;
constexpr int MR = B * S;          // 8192
}

// ---------------- scratch (__device__ globals; no allocations) -------------
__device__ float g_v[cfg::MR * cfg::D];
__device__ float g_p[(long long)cfg::B * cfg::S * cfg::S];

// bf16 hi/lo planes, stored as [rows][2K] = [hi(0..K-1) | lo(0..K-1)]
__device__ unsigned short g_x2 [(long long)cfg::MR * 2 * cfg::D];
__device__ unsigned short g_wq2[(long long)cfg::D  * 2 * cfg::D];   // [n][2K], W^T
__device__ unsigned short g_wk2[(long long)cfg::D  * 2 * cfg::D];
__device__ unsigned short g_wv2[(long long)cfg::D  * 2 * cfg::D];
__device__ unsigned short g_q2 [(long long)cfg::MR * 2 * cfg::D];
__device__ unsigned short g_k2 [(long long)cfg::MR * 2 * cfg::D];
__device__ unsigned short g_v2t[(long long)cfg::B * cfg::D * 2 * cfg::S]; // [b][d][2S], V^T
__device__ unsigned short g_p2 [(long long)cfg::B * cfg::S * 2 * cfg::S];

// ---------------- PTX helpers ----------------------------------------------
__device__ __forceinline__ uint32_t smem_u32(const void* p) {
    uint32_t a;
    asm("{ .reg .u64 t; cvta.to.shared.u64 t, %1; cvt.u32.u64 %0, t; }"
        : "=r"(a) : "l"(p));
    return a;
}

#define CP_ASYNC_16(dst, src)                                                 \
    asm volatile("cp.async.cg.shared.global [%0], [%1], 16;"                  \
                 :: "r"(dst), "l"(src))
#define CP_COMMIT() asm volatile("cp.async.commit_group;" ::: "memory")
#define CP_WAIT_1() asm volatile("cp.async.wait_group 1;" ::: "memory")
#define CP_WAIT_0() asm volatile("cp.async.wait_group 0;" ::: "memory")

#define LDSM_X4(r0, r1, r2, r3, addr)                                         \
    asm volatile("ldmatrix.sync.aligned.m8n8.x4.shared.b16 {%0,%1,%2,%3}, [%4];" \
                 : "=r"(r0), "=r"(r1), "=r"(r2), "=r"(r3) : "r"(addr))

#define MMA_BF16(d, a, b)                                                     \
    asm volatile("mma.sync.aligned.m16n8k16.row.col.f32.bf16.bf16.f32 "       \
                 "{%0,%1,%2,%3},{%4,%5,%6,%7},{%8,%9},{%0,%1,%2,%3};"         \
                 : "+f"((d)[0]), "+f"((d)[1]), "+f"((d)[2]), "+f"((d)[3])     \
                 : "r"((a)[0]), "r"((a)[1]), "r"((a)[2]), "r"((a)[3]),        \
                   "r"((b)[0]), "r"((b)[1]))

// ---------------- hi/lo split helper ---------------------------------------
__device__ __forceinline__ void split1(float v, unsigned short& h, unsigned short& l) {
    __nv_bfloat16 hb = __float2bfloat16(v);
    float rem = v - __bfloat162float(hb);
    __nv_bfloat16 lb = __float2bfloat16(rem);
    h = __bfloat16_as_ushort(hb);
    l = __bfloat16_as_ushort(lb);
}

// fp32 [rows][K] -> bf16 [rows][2K] (hi plane | lo plane)
__global__ __launch_bounds__(256) void conv_split(
    const float* __restrict__ in, unsigned short* __restrict__ out,
    unsigned int total4, unsigned int Kq /* = K/4 */, int K)
{
    for (unsigned int i = blockIdx.x * blockDim.x + threadIdx.x; i < total4;
         i += gridDim.x * blockDim.x) {
        unsigned int r = i / Kq;
        unsigned int c4 = i - r * Kq;
        float4 v = *(const float4*)(in + (long long)r * K + c4 * 4);
        unsigned short h0, h1, h2, h3, l0, l1, l2, l3;
        split1(v.x, h0, l0); split1(v.y, h1, l1);
        split1(v.z, h2, l2); split1(v.w, h3, l3);
        uint2 hv, lv;
        hv.x = (uint32_t)h0 | ((uint32_t)h1 << 16);
        hv.y = (uint32_t)h2 | ((uint32_t)h3 << 16);
        lv.x = (uint32_t)l0 | ((uint32_t)l1 << 16);
        lv.y = (uint32_t)l2 | ((uint32_t)l3 << 16);
        unsigned short* orow = out + (long long)r * 2 * K;
        *(uint2*)(orow + c4 * 4)     = hv;
        *(uint2*)(orow + K + c4 * 4) = lv;
    }
}

// fp32 [Krows][Ncols] -> bf16 [Ncols][2*Krows] transposed hi/lo (for W^T, V^T)
// zmode=1: blockIdx.z selects tensor (weights fused); zmode=0: z is batch.
__global__ __launch_bounds__(256) void conv_split_T(
    const float* __restrict__ in0, const float* __restrict__ in1,
    const float* __restrict__ in2,
    unsigned short* __restrict__ out0, unsigned short* __restrict__ out1,
    unsigned short* __restrict__ out2,
    int Krows, int Ncols, long long sIn, long long sOut, int zmode)
{
    __shared__ float t[32][33];
    const float* ib;
    unsigned short* ob;
    if (zmode) {
        ib = (blockIdx.z == 0) ? in0 : (blockIdx.z == 1) ? in1 : in2;
        ob = (blockIdx.z == 0) ? out0 : (blockIdx.z == 1) ? out1 : out2;
    } else {
        ib = in0 + (long long)blockIdx.z * sIn;
        ob = out0 + (long long)blockIdx.z * sOut;
    }
    const int k0 = blockIdx.y * 32, n0 = blockIdx.x * 32;
    const int tx = threadIdx.x, ty = threadIdx.y;     // (32, 8)
#pragma unroll
    for (int i = 0; i < 4; i++)
        t[ty + i * 8][tx] = ib[(long long)(k0 + ty + i * 8) * Ncols + n0 + tx];
    __syncthreads();
    const int ld2 = 2 * Krows;
#pragma unroll
    for (int i = 0; i < 4; i++) {
        int n = n0 + ty + i * 8;
        int k = k0 + tx;
        unsigned short h, l;
        split1(t[tx][ty + i * 8], h, l);
        ob[(long long)n * ld2 + k]         = h;
        ob[(long long)n * ld2 + Krows + k] = l;
    }
}

// ===========================================================================
// mma.sync GEMM: C[m,n] = sum over 3 bf16 term-pairs of A2,B2 (+bias)
//   A2: [M][2K] hi|lo, segments {hi,hi,lo};  B2: [N][2K] hi|lo, segs {hi,lo,hi}
// CTA tile 128x128, 4 warps, warp tile 64x64 (2x2 grid), BK=64, 3-stage,
// next-next chunk staged mid-chunk.
// m-tile index = yIdx*yStride + yBase (parity splits); KBOUND reverses y
// (longest K-loop first) for wave packing; CAUSAL_SKIP drops masked tiles.
// EPI_SPLIT: C is ushort* [M][2N] hi|lo (fused output split for Q/K).
// ===========================================================================
template <bool HAS_BIAS, bool CAUSAL_SKIP, bool KBOUND, bool EPI_SPLIT>
__global__ __launch_bounds__(128, 2) void mma_gemm(
    const unsigned short* __restrict__ A2, const unsigned short* __restrict__ B2,
    const float* __restrict__ bias, void* __restrict__ Cv,
    int Ndim, int Kdim, long long sA, long long sB, long long sC,
    int yStride, int yBase)
{
    const int yIdx = KBOUND ? (gridDim.y - 1 - blockIdx.y) : blockIdx.y;
    const int m0 = (yIdx * yStride + yBase) * 128;
    const int n0 = blockIdx.x * 128;
    if (CAUSAL_SKIP && n0 > m0 + 127) return;

    extern __shared__ char dynsmem[];
    const uint32_t sb = smem_u32(dynsmem);

    const int tid  = threadIdx.x;
    const int lane = tid & 31;
    const int warp = tid >> 5;
    const int wm   = warp >> 1;       // 0..1
    const int wn   = warp & 1;        // 0..1

    const long long ldAe = 2LL * Kdim;            // elements per row
    const long long ldBytes = ldAe * 2;
    const char* baseA = (const char*)(A2 + (long long)blockIdx.z * sA + (long long)m0 * ldAe);
    const char* baseB = (const char*)(B2 + (long long)blockIdx.z * sB + (long long)n0 * ldAe);

    const int segK = KBOUND ? (m0 + 128) : Kdim;
    const int nps = segK >> 6;                    // 64-elem chunks per segment
    const int nChunks = 3 * nps;

    // ---- staging mapping: 128 threads; thread -> (row, 16B unit)
    const int srow = tid >> 3;                    // 0..15
    const int su   = tid & 7;                     // 0..7
    const uint32_t sdst = (uint32_t)(srow * 128 + ((su ^ (srow & 7)) << 4));
    const long long sgoff = (long long)srow * ldBytes + su * 16;

    auto stage = [&](int c, int buf) {
        const int seg = c / nps, kc = c - seg * nps;
        const long long offA = ((long long)kc * 64 + (seg == 2 ? (long long)Kdim : 0)) * 2;
        const long long offB = ((long long)kc * 64 + (seg == 1 ? (long long)Kdim : 0)) * 2;
        const char* ga = baseA + offA + sgoff;
        const char* gb = baseB + offB + sgoff;
        const uint32_t da = sb + buf * 32768u + sdst;
        const uint32_t db = da + 16384u;
#pragma unroll
        for (int i = 0; i < 8; i++) {     // 128 rows each, 16 apart
            CP_ASYNC_16(da + i * 2048u, ga + (long long)i * 16 * ldBytes);
            CP_ASYNC_16(db + i * 2048u, gb + (long long)i * 16 * ldBytes);
        }
        CP_COMMIT();
    };

    float acc[4][8][4];
#pragma unroll
    for (int i = 0; i < 4; i++)
#pragma unroll
        for (int j = 0; j < 8; j++)
#pragma unroll
            for (int t = 0; t < 4; t++) acc[i][j][t] = 0.f;

    // per-lane ldmatrix address components (XOR swizzle: chunk ^= row&7)
    const uint32_t aRowBase = (uint32_t)(wm * 64 + (lane & 15));
    const uint32_t aChunkX  = (uint32_t)(lane >> 4);
    const uint32_t bRowBase = (uint32_t)(wn * 64 + (lane & 7) + ((lane & 16) >> 1));
    const uint32_t bChunkX  = (uint32_t)((lane >> 3) & 1);
    const uint32_t lxor     = (uint32_t)(lane & 7);

    stage(0, 0);
    stage(1, 1);

    for (int c = 0; c < nChunks; c++) {
        if (c + 1 < nChunks) { CP_WAIT_1(); } else { CP_WAIT_0(); }
        __syncthreads();

        const uint32_t sAb = sb + (uint32_t)(c % 3) * 32768u;
        const uint32_t sBb = sAb + 16384u;

        auto compute_s = [&](int s) {
            uint32_t a[4][4];
            uint32_t b[4][4];          // [nb2][{b0lo,b0hi,b1lo,b1hi}]
#pragma unroll
            for (int mb = 0; mb < 4; mb++) {
                const uint32_t addr = sAb + (aRowBase + mb * 16) * 128u
                                    + (((s * 2 + aChunkX) ^ lxor) << 4);
                LDSM_X4(a[mb][0], a[mb][1], a[mb][2], a[mb][3], addr);
            }
#pragma unroll
            for (int nb2 = 0; nb2 < 4; nb2++) {
                const uint32_t addr = sBb + (bRowBase + nb2 * 16) * 128u
                                    + (((s * 2 + bChunkX) ^ lxor) << 4);
                LDSM_X4(b[nb2][0], b[nb2][1], b[nb2][2], b[nb2][3], addr);
            }
#pragma unroll
            for (int nb2 = 0; nb2 < 4; nb2++)
#pragma unroll
                for (int mb = 0; mb < 4; mb++) {
                    MMA_BF16(acc[mb][nb2 * 2],     a[mb], &b[nb2][0]);
                    MMA_BF16(acc[mb][nb2 * 2 + 1], a[mb], &b[nb2][2]);
                }
        };

        compute_s(0);
        compute_s(1);
        if (c + 2 < nChunks) stage(c + 2, (c + 2) % 3);  // mid-chunk prefetch
        compute_s(2);
        compute_s(3);
    }

    // ---- epilogue ----------------------------------------------------------
    const int rBase = m0 + wm * 64 + (lane >> 2);
    const int cBase = n0 + wn * 64 + (lane & 3) * 2;

    if (EPI_SPLIT) {
        unsigned short* Cs = (unsigned short*)Cv + (long long)blockIdx.z * sC;
#pragma unroll
        for (int nb = 0; nb < 8; nb++) {
            const int cc = cBase + nb * 8;
            float bx = 0.f, by = 0.f;
            if (HAS_BIAS) { bx = bias[cc]; by = bias[cc + 1]; }
#pragma unroll
            for (int mb = 0; mb < 4; mb++) {
                const int r = rBase + mb * 16;
#pragma unroll
                for (int half = 0; half < 2; half++) {
                    const float v0 = acc[mb][nb][half * 2]     + bx;
                    const float v1 = acc[mb][nb][half * 2 + 1] + by;
                    unsigned short h0, l0, h1, l1;
                    split1(v0, h0, l0);
                    split1(v1, h1, l1);
                    unsigned short* row = Cs + (long long)(r + half * 8) * (2 * Ndim);
                    *(uint32_t*)(row + cc)        = (uint32_t)h0 | ((uint32_t)h1 << 16);
                    *(uint32_t*)(row + Ndim + cc) = (uint32_t)l0 | ((uint32_t)l1 << 16);
                }
            }
        }
    } else {
        float* Cb = (float*)Cv + (long long)blockIdx.z * sC;
#pragma unroll
        for (int nb = 0; nb < 8; nb++) {
            const int cc = cBase + nb * 8;
            float bx = 0.f, by = 0.f;
            if (HAS_BIAS) { bx = bias[cc]; by = bias[cc + 1]; }
#pragma unroll
            for (int mb = 0; mb < 4; mb++) {
                const int r = rBase + mb * 16;
                float2 v0, v1;
                v0.x = acc[mb][nb][0] + bx; v0.y = acc[mb][nb][1] + by;
                v1.x = acc[mb][nb][2] + bx; v1.y = acc[mb][nb][3] + by;
                *(float2*)(Cb + (long long)r * Ndim + cc)       = v0;
                *(float2*)(Cb + (long long)(r + 8) * Ndim + cc) = v1;
            }
        }
    }
}

// ===========================================================================
// Register-resident causal softmax, emits bf16 hi/lo split planes directly.
// parity selects which 128-row tiles this launch handles (q/128 parity).
// Grid = B * S/2 blocks. Loads only [0, blockEnd) of the row.
// ===========================================================================
__global__ __launch_bounds__(256) void softmax_split(
    const float* __restrict__ P, unsigned short* __restrict__ P2, int parity)
{
    using namespace cfg;
    const int idx = blockIdx.x;              // 0 .. B*S/2-1
    const int b   = idx >> 10;               // S/2 = 1024 rows per batch half
    const int r   = idx & 1023;
    const int q   = (((r >> 7) << 1) + parity) * 128 + (r & 127);
    const float* src = P + (long long)b * S * S + (long long)q * S;
    unsigned short* dst = P2 + ((long long)b * S + q) * (2 * S);
    const int len = q + 1;
    const int blockEnd = ((q >> 7) + 1) << 7;
    const int tid = threadIdx.x;

    __shared__ float red[256];

    float v[8];
#pragma unroll
    for (int j = 0; j < 2; j++) {
        const int i0 = (tid + j * 256) * 4;
        if (i0 < blockEnd) {
            *(float4*)&v[j * 4] = *(const float4*)(src + i0);
        } else {
            v[j * 4] = v[j * 4 + 1] = v[j * 4 + 2] = v[j * 4 + 3] = 0.f;
        }
    }

    float m = -3.4e38f;
#pragma unroll
    for (int j = 0; j < 2; j++)
#pragma unroll
        for (int t = 0; t < 4; t++) {
            const int i = (tid + j * 256) * 4 + t;
            if (i < len) m = fmaxf(m, v[j * 4 + t]);
        }
    red[tid] = m;
    __syncthreads();
#pragma unroll
    for (int s2 = 128; s2 > 0; s2 >>= 1) {
        if (tid < s2) red[tid] = fmaxf(red[tid], red[tid + s2]);
        __syncthreads();
    }
    m = red[0];
    __syncthreads();

    float e[8];
    float sum = 0.f;
#pragma unroll
    for (int j = 0; j < 2; j++)
#pragma unroll
        for (int t = 0; t < 4; t++) {
            const int i = (tid + j * 256) * 4 + t;
            const float ev = (i < len) ? __expf(v[j * 4 + t] - m) : 0.f;
            e[j * 4 + t] = ev;
            sum += ev;
        }
    red[tid] = sum;
    __syncthreads();
#pragma unroll
    for (int s2 = 128; s2 > 0; s2 >>= 1) {
        if (tid < s2) red[tid] += red[tid + s2];
        __syncthreads();
    }
    const float inv = 1.f / red[0];

#pragma unroll
    for (int j = 0; j < 2; j++) {
        const int i = (tid + j * 256) * 4;
        if (i < blockEnd) {
            unsigned short h[4], l[4];
#pragma unroll
            for (int t = 0; t < 4; t++) split1(e[j * 4 + t] * inv, h[t], l[t]);
            uint2 hv, lv;
            hv.x = (uint32_t)h[0] | ((uint32_t)h[1] << 16);
            hv.y = (uint32_t)h[2] | ((uint32_t)h[3] << 16);
            lv.x = (uint32_t)l[0] | ((uint32_t)l[1] << 16);
            lv.y = (uint32_t)l[2] | ((uint32_t)l[3] << 16);
            *(uint2*)(dst + i)     = hv;
            *(uint2*)(dst + S + i) = lv;
        }
    }
}

// ---------------- persistent stream/event pool (lazy, one-time) ------------
struct StreamPool {
    cudaStream_t s1, s2;
    cudaEvent_t eFork, eK, eV, eSA, eJ;
    StreamPool() {
        cudaStreamCreateWithFlags(&s1, cudaStreamNonBlocking);
        cudaStreamCreateWithFlags(&s2, cudaStreamNonBlocking);
        cudaEventCreateWithFlags(&eFork, cudaEventDisableTiming);
        cudaEventCreateWithFlags(&eK,    cudaEventDisableTiming);
        cudaEventCreateWithFlags(&eV,    cudaEventDisableTiming);
        cudaEventCreateWithFlags(&eSA,   cudaEventDisableTiming);
        cudaEventCreateWithFlags(&eJ,    cudaEventDisableTiming);
    }
};
static StreamPool& pool() { static StreamPool p; return p; }

// ===========================================================================
// launch — forked-stream capture with parity pipelines (best measured):
//   main: convX, convW -> projQ -> scoresA(odd) -> softmaxA -> PVA(odd)
//   s1:   projK ; then scoresB(even) -> softmaxB -> PVB(even)
//   s2:   projV -> conv V^T
// ===========================================================================
extern "C" void kernel_launch(void* const* d_in, const int* in_sizes, int n_in,
                              void* d_out, int out_size)
{
    using namespace cfg;
    const float* x  = (const float*)d_in[0];
    const float* Wq = (const float*)d_in[1];
    const float* bq = (const float*)d_in[2];
    const float* Wk = (const float*)d_in[3];
    const float* bk = (const float*)d_in[4];
    const float* Wv = (const float*)d_in[5];
    const float* bv = (const float*)d_in[6];
    float* out = (float*)d_out;

    float *v, *p;
    unsigned short *x2, *wq2, *wk2, *wv2, *q2, *k2, *v2t, *p2;
    cudaGetSymbolAddress((void**)&v, g_v);
    cudaGetSymbolAddress((void**)&p, g_p);
    cudaGetSymbolAddress((void**)&x2,  g_x2);
    cudaGetSymbolAddress((void**)&wq2, g_wq2);
    cudaGetSymbolAddress((void**)&wk2, g_wk2);
    cudaGetSymbolAddress((void**)&wv2, g_wv2);
    cudaGetSymbolAddress((void**)&q2,  g_q2);
    cudaGetSymbolAddress((void**)&k2,  g_k2);
    cudaGetSymbolAddress((void**)&v2t, g_v2t);
    cudaGetSymbolAddress((void**)&p2,  g_p2);

    const int SMEM_DYN = 98304;   // 3 stages x (16KB A + 16KB B)
    cudaFuncSetAttribute(mma_gemm<true,  false, false, true>,
                         cudaFuncAttributeMaxDynamicSharedMemorySize, SMEM_DYN);
    cudaFuncSetAttribute(mma_gemm<true,  false, false, false>,
                         cudaFuncAttributeMaxDynamicSharedMemorySize, SMEM_DYN);
    cudaFuncSetAttribute(mma_gemm<false, true,  false, false>,
                         cudaFuncAttributeMaxDynamicSharedMemorySize, SMEM_DYN);
    cudaFuncSetAttribute(mma_gemm<false, false, true,  false>,
                         cudaFuncAttributeMaxDynamicSharedMemorySize, SMEM_DYN);

    StreamPool& sp = pool();   // created on first (correctness) call only

    // ---- main stream: input splits --------------------------------------
    conv_split<<<8192, 256>>>(x, x2, (unsigned)(MR * D / 4), (unsigned)(D / 4), D);
    {
        dim3 g(D / 32, D / 32, 3), b2(32, 8);
        conv_split_T<<<g, b2>>>(Wq, Wk, Wv, wq2, wk2, wv2, D, D, 0, 0, 1);
    }
    cudaEventRecord(sp.eFork, 0);
    cudaStreamWaitEvent(sp.s1, sp.eFork, 0);
    cudaStreamWaitEvent(sp.s2, sp.eFork, 0);

    // ---- projections: Q main, K on s1, V (+transpose) on s2 -------------
    {
        dim3 g(D / 128, MR / 128, 1), b2(128);
        mma_gemm<true, false, false, true ><<<g, b2, SMEM_DYN, 0    >>>(x2, wq2, bq, q2, D, D, 0, 0, 0, 1, 0);
        mma_gemm<true, false, false, true ><<<g, b2, SMEM_DYN, sp.s1>>>(x2, wk2, bk, k2, D, D, 0, 0, 0, 1, 0);
        mma_gemm<true, false, false, false><<<g, b2, SMEM_DYN, sp.s2>>>(x2, wv2, bv, v,  D, D, 0, 0, 0, 1, 0);
    }
    {   // V^T hi/lo per batch, stays on s2
        dim3 g(D / 32, S / 32, B), b2(32, 8);
        conv_split_T<<<g, b2, 0, sp.s2>>>(v, nullptr, nullptr, v2t, nullptr, nullptr,
                                          S, D, (long long)S * D, (long long)D * 2 * S, 0);
    }
    cudaEventRecord(sp.eK, sp.s1);
    cudaEventRecord(sp.eV, sp.s2);

    const long long sAsc = (long long)S * 2 * D, sCsc = (long long)S * S;
    const long long sApv = (long long)S * 2 * S, sBpv = (long long)D * 2 * S;
    const long long sCpv = (long long)S * D;

    // ---- scoresA (odd y-tiles) on main: needs Q (main) and K (s1) --------
    cudaStreamWaitEvent(0, sp.eK, 0);
    {
        dim3 g(S / 128, 8, B), b2(128);
        mma_gemm<false, true, false, false><<<g, b2, SMEM_DYN>>>(
            q2, k2, nullptr, p, S, D, sAsc, sAsc, sCsc, 2, 1);
    }
    cudaEventRecord(sp.eSA, 0);

    // ---- s1: scoresB (even) -> softmaxB -> PVB (even) --------------------
    cudaStreamWaitEvent(sp.s1, sp.eSA, 0);
    {
        dim3 g(S / 128, 8, B), b2(128);
        mma_gemm<false, true, false, false><<<g, b2, SMEM_DYN, sp.s1>>>(
            q2, k2, nullptr, p, S, D, sAsc, sAsc, sCsc, 2, 0);
    }
    softmax_split<<<B * S / 2, 256, 0, sp.s1>>>(p, p2, 0);
    cudaStreamWaitEvent(sp.s1, sp.eV, 0);
    {
        dim3 g(D / 128, 8, B), b2(128);
        mma_gemm<false, false, true, false><<<g, b2, SMEM_DYN, sp.s1>>>(
            p2, v2t, nullptr, out, D, S, sApv, sBpv, sCpv, 2, 0);
    }
    cudaEventRecord(sp.eJ, sp.s1);

    // ---- main: softmaxA (odd) -> PVA (odd) --------------------------------
    softmax_split<<<B * S / 2, 256>>>(p, p2, 1);
    cudaStreamWaitEvent(0, sp.eV, 0);
    {
        dim3 g(D / 128, 8, B), b2(128);
        mma_gemm<false, false, true, false><<<g, b2, SMEM_DYN>>>(
            p2, v2t, nullptr, out, D, S, sApv, sBpv, sCpv, 2, 1);
    }
    cudaStreamWaitEvent(0, sp.eJ, 0);   // join s1 back into main
}

// round 16
// speedup vs baseline: 1.0581x; 1.0065x over previous
#include <cuda_runtime.h>
#include <cuda_bf16.h>
#include <cstdint>

// ===========================================================================
// Causal self-attention via mma.sync bf16 (sm_103 non-'a' compatible).
// All GEMMs: bf16 3-term hi/lo split (fp32-accurate), fp32 accumulate.
// GEMM: CTA tile 128x128, 4 warps (warp tile 64x64), BK=64, 3-stage cp.async
//       (staged mid-chunk), 2 CTAs/SM.
// Schedule (best measured): parity-split scores/softmax/PV pipelines on two
// streams; K-proj on s1, V-proj+V^T on s2; convX/convW serial pre-fork.
// Softmax: warp-shuffle reductions (4 barriers instead of 16).
// ===========================================================================

namespace cfg {
constexpr int B = 4;
constexpr int S = 2048;
constexpr int D = 1024;
constexpr int MR = B * S;          // 8192
}

// ---------------- scratch (__device__ globals; no allocations) -------------
__device__ float g_v[cfg::MR * cfg::D];
__device__ float g_p[(long long)cfg::B * cfg::S * cfg::S];

// bf16 hi/lo planes, stored as [rows][2K] = [hi(0..K-1) | lo(0..K-1)]
__device__ unsigned short g_x2 [(long long)cfg::MR * 2 * cfg::D];
__device__ unsigned short g_wq2[(long long)cfg::D  * 2 * cfg::D];   // [n][2K], W^T
__device__ unsigned short g_wk2[(long long)cfg::D  * 2 * cfg::D];
__device__ unsigned short g_wv2[(long long)cfg::D  * 2 * cfg::D];
__device__ unsigned short g_q2 [(long long)cfg::MR * 2 * cfg::D];
__device__ unsigned short g_k2 [(long long)cfg::MR * 2 * cfg::D];
__device__ unsigned short g_v2t[(long long)cfg::B * cfg::D * 2 * cfg::S]; // [b][d][2S], V^T
__device__ unsigned short g_p2 [(long long)cfg::B * cfg::S * 2 * cfg::S];

// ---------------- PTX helpers ----------------------------------------------
__device__ __forceinline__ uint32_t smem_u32(const void* p) {
    uint32_t a;
    asm("{ .reg .u64 t; cvta.to.shared.u64 t, %1; cvt.u32.u64 %0, t; }"
        : "=r"(a) : "l"(p));
    return a;
}

#define CP_ASYNC_16(dst, src)                                                 \
    asm volatile("cp.async.cg.shared.global [%0], [%1], 16;"                  \
                 :: "r"(dst), "l"(src))
#define CP_COMMIT() asm volatile("cp.async.commit_group;" ::: "memory")
#define CP_WAIT_1() asm volatile("cp.async.wait_group 1;" ::: "memory")
#define CP_WAIT_0() asm volatile("cp.async.wait_group 0;" ::: "memory")

#define LDSM_X4(r0, r1, r2, r3, addr)                                         \
    asm volatile("ldmatrix.sync.aligned.m8n8.x4.shared.b16 {%0,%1,%2,%3}, [%4];" \
                 : "=r"(r0), "=r"(r1), "=r"(r2), "=r"(r3) : "r"(addr))

#define MMA_BF16(d, a, b)                                                     \
    asm volatile("mma.sync.aligned.m16n8k16.row.col.f32.bf16.bf16.f32 "       \
                 "{%0,%1,%2,%3},{%4,%5,%6,%7},{%8,%9},{%0,%1,%2,%3};"         \
                 : "+f"((d)[0]), "+f"((d)[1]), "+f"((d)[2]), "+f"((d)[3])     \
                 : "r"((a)[0]), "r"((a)[1]), "r"((a)[2]), "r"((a)[3]),        \
                   "r"((b)[0]), "r"((b)[1]))

// ---------------- hi/lo split helper ---------------------------------------
__device__ __forceinline__ void split1(float v, unsigned short& h, unsigned short& l) {
    __nv_bfloat16 hb = __float2bfloat16(v);
    float rem = v - __bfloat162float(hb);
    __nv_bfloat16 lb = __float2bfloat16(rem);
    h = __bfloat16_as_ushort(hb);
    l = __bfloat16_as_ushort(lb);
}

// fp32 [rows][K] -> bf16 [rows][2K] (hi plane | lo plane)
__global__ __launch_bounds__(256) void conv_split(
    const float* __restrict__ in, unsigned short* __restrict__ out,
    unsigned int total4, unsigned int Kq /* = K/4 */, int K)
{
    for (unsigned int i = blockIdx.x * blockDim.x + threadIdx.x; i < total4;
         i += gridDim.x * blockDim.x) {
        unsigned int r = i / Kq;
        unsigned int c4 = i - r * Kq;
        float4 v = *(const float4*)(in + (long long)r * K + c4 * 4);
        unsigned short h0, h1, h2, h3, l0, l1, l2, l3;
        split1(v.x, h0, l0); split1(v.y, h1, l1);
        split1(v.z, h2, l2); split1(v.w, h3, l3);
        uint2 hv, lv;
        hv.x = (uint32_t)h0 | ((uint32_t)h1 << 16);
        hv.y = (uint32_t)h2 | ((uint32_t)h3 << 16);
        lv.x = (uint32_t)l0 | ((uint32_t)l1 << 16);
        lv.y = (uint32_t)l2 | ((uint32_t)l3 << 16);
        unsigned short* orow = out + (long long)r * 2 * K;
        *(uint2*)(orow + c4 * 4)     = hv;
        *(uint2*)(orow + K + c4 * 4) = lv;
    }
}

// fp32 [Krows][Ncols] -> bf16 [Ncols][2*Krows] transposed hi/lo (for W^T, V^T)
// zmode=1: blockIdx.z selects tensor (weights fused); zmode=0: z is batch.
__global__ __launch_bounds__(256) void conv_split_T(
    const float* __restrict__ in0, const float* __restrict__ in1,
    const float* __restrict__ in2,
    unsigned short* __restrict__ out0, unsigned short* __restrict__ out1,
    unsigned short* __restrict__ out2,
    int Krows, int Ncols, long long sIn, long long sOut, int zmode)
{
    __shared__ float t[32][33];
    const float* ib;
    unsigned short* ob;
    if (zmode) {
        ib = (blockIdx.z == 0) ? in0 : (blockIdx.z == 1) ? in1 : in2;
        ob = (blockIdx.z == 0) ? out0 : (blockIdx.z == 1) ? out1 : out2;
    } else {
        ib = in0 + (long long)blockIdx.z * sIn;
        ob = out0 + (long long)blockIdx.z * sOut;
    }
    const int k0 = blockIdx.y * 32, n0 = blockIdx.x * 32;
    const int tx = threadIdx.x, ty = threadIdx.y;     // (32, 8)
#pragma unroll
    for (int i = 0; i < 4; i++)
        t[ty + i * 8][tx] = ib[(long long)(k0 + ty + i * 8) * Ncols + n0 + tx];
    __syncthreads();
    const int ld2 = 2 * Krows;
#pragma unroll
    for (int i = 0; i < 4; i++) {
        int n = n0 + ty + i * 8;
        int k = k0 + tx;
        unsigned short h, l;
        split1(t[tx][ty + i * 8], h, l);
        ob[(long long)n * ld2 + k]         = h;
        ob[(long long)n * ld2 + Krows + k] = l;
    }
}

// ===========================================================================
// mma.sync GEMM: C[m,n] = sum over 3 bf16 term-pairs of A2,B2 (+bias)
//   A2: [M][2K] hi|lo, segments {hi,hi,lo};  B2: [N][2K] hi|lo, segs {hi,lo,hi}
// CTA tile 128x128, 4 warps, warp tile 64x64 (2x2 grid), BK=64, 3-stage,
// next-next chunk staged mid-chunk.
// m-tile index = yIdx*yStride + yBase (parity splits); KBOUND reverses y
// (longest K-loop first) for wave packing; CAUSAL_SKIP drops masked tiles.
// EPI_SPLIT: C is ushort* [M][2N] hi|lo (fused output split for Q/K).
// ===========================================================================
template <bool HAS_BIAS, bool CAUSAL_SKIP, bool KBOUND, bool EPI_SPLIT>
__global__ __launch_bounds__(128, 2) void mma_gemm(
    const unsigned short* __restrict__ A2, const unsigned short* __restrict__ B2,
    const float* __restrict__ bias, void* __restrict__ Cv,
    int Ndim, int Kdim, long long sA, long long sB, long long sC,
    int yStride, int yBase)
{
    const int yIdx = KBOUND ? (gridDim.y - 1 - blockIdx.y) : blockIdx.y;
    const int m0 = (yIdx * yStride + yBase) * 128;
    const int n0 = blockIdx.x * 128;
    if (CAUSAL_SKIP && n0 > m0 + 127) return;

    extern __shared__ char dynsmem[];
    const uint32_t sb = smem_u32(dynsmem);

    const int tid  = threadIdx.x;
    const int lane = tid & 31;
    const int warp = tid >> 5;
    const int wm   = warp >> 1;       // 0..1
    const int wn   = warp & 1;        // 0..1

    const long long ldAe = 2LL * Kdim;            // elements per row
    const long long ldBytes = ldAe * 2;
    const char* baseA = (const char*)(A2 + (long long)blockIdx.z * sA + (long long)m0 * ldAe);
    const char* baseB = (const char*)(B2 + (long long)blockIdx.z * sB + (long long)n0 * ldAe);

    const int segK = KBOUND ? (m0 + 128) : Kdim;
    const int nps = segK >> 6;                    // 64-elem chunks per segment
    const int nChunks = 3 * nps;

    // ---- staging mapping: 128 threads; thread -> (row, 16B unit)
    const int srow = tid >> 3;                    // 0..15
    const int su   = tid & 7;                     // 0..7
    const uint32_t sdst = (uint32_t)(srow * 128 + ((su ^ (srow & 7)) << 4));
    const long long sgoff = (long long)srow * ldBytes + su * 16;

    auto stage = [&](int c, int buf) {
        const int seg = c / nps, kc = c - seg * nps;
        const long long offA = ((long long)kc * 64 + (seg == 2 ? (long long)Kdim : 0)) * 2;
        const long long offB = ((long long)kc * 64 + (seg == 1 ? (long long)Kdim : 0)) * 2;
        const char* ga = baseA + offA + sgoff;
        const char* gb = baseB + offB + sgoff;
        const uint32_t da = sb + buf * 32768u + sdst;
        const uint32_t db = da + 16384u;
#pragma unroll
        for (int i = 0; i < 8; i++) {     // 128 rows each, 16 apart
            CP_ASYNC_16(da + i * 2048u, ga + (long long)i * 16 * ldBytes);
            CP_ASYNC_16(db + i * 2048u, gb + (long long)i * 16 * ldBytes);
        }
        CP_COMMIT();
    };

    float acc[4][8][4];
#pragma unroll
    for (int i = 0; i < 4; i++)
#pragma unroll
        for (int j = 0; j < 8; j++)
#pragma unroll
            for (int t = 0; t < 4; t++) acc[i][j][t] = 0.f;

    // per-lane ldmatrix address components (XOR swizzle: chunk ^= row&7)
    const uint32_t aRowBase = (uint32_t)(wm * 64 + (lane & 15));
    const uint32_t aChunkX  = (uint32_t)(lane >> 4);
    const uint32_t bRowBase = (uint32_t)(wn * 64 + (lane & 7) + ((lane & 16) >> 1));
    const uint32_t bChunkX  = (uint32_t)((lane >> 3) & 1);
    const uint32_t lxor     = (uint32_t)(lane & 7);

    stage(0, 0);
    stage(1, 1);

    for (int c = 0; c < nChunks; c++) {
        if (c + 1 < nChunks) { CP_WAIT_1(); } else { CP_WAIT_0(); }
        __syncthreads();

        const uint32_t sAb = sb + (uint32_t)(c % 3) * 32768u;
        const uint32_t sBb = sAb + 16384u;

        auto compute_s = [&](int s) {
            uint32_t a[4][4];
            uint32_t b[4][4];          // [nb2][{b0lo,b0hi,b1lo,b1hi}]
#pragma unroll
            for (int mb = 0; mb < 4; mb++) {
                const uint32_t addr = sAb + (aRowBase + mb * 16) * 128u
                                    + (((s * 2 + aChunkX) ^ lxor) << 4);
                LDSM_X4(a[mb][0], a[mb][1], a[mb][2], a[mb][3], addr);
            }
#pragma unroll
            for (int nb2 = 0; nb2 < 4; nb2++) {
                const uint32_t addr = sBb + (bRowBase + nb2 * 16) * 128u
                                    + (((s * 2 + bChunkX) ^ lxor) << 4);
                LDSM_X4(b[nb2][0], b[nb2][1], b[nb2][2], b[nb2][3], addr);
            }
#pragma unroll
            for (int nb2 = 0; nb2 < 4; nb2++)
#pragma unroll
                for (int mb = 0; mb < 4; mb++) {
                    MMA_BF16(acc[mb][nb2 * 2],     a[mb], &b[nb2][0]);
                    MMA_BF16(acc[mb][nb2 * 2 + 1], a[mb], &b[nb2][2]);
                }
        };

        compute_s(0);
        compute_s(1);
        if (c + 2 < nChunks) stage(c + 2, (c + 2) % 3);  // mid-chunk prefetch
        compute_s(2);
        compute_s(3);
    }

    // ---- epilogue ----------------------------------------------------------
    const int rBase = m0 + wm * 64 + (lane >> 2);
    const int cBase = n0 + wn * 64 + (lane & 3) * 2;

    if (EPI_SPLIT) {
        unsigned short* Cs = (unsigned short*)Cv + (long long)blockIdx.z * sC;
#pragma unroll
        for (int nb = 0; nb < 8; nb++) {
            const int cc = cBase + nb * 8;
            float bx = 0.f, by = 0.f;
            if (HAS_BIAS) { bx = bias[cc]; by = bias[cc + 1]; }
#pragma unroll
            for (int mb = 0; mb < 4; mb++) {
                const int r = rBase + mb * 16;
#pragma unroll
                for (int half = 0; half < 2; half++) {
                    const float v0 = acc[mb][nb][half * 2]     + bx;
                    const float v1 = acc[mb][nb][half * 2 + 1] + by;
                    unsigned short h0, l0, h1, l1;
                    split1(v0, h0, l0);
                    split1(v1, h1, l1);
                    unsigned short* row = Cs + (long long)(r + half * 8) * (2 * Ndim);
                    *(uint32_t*)(row + cc)        = (uint32_t)h0 | ((uint32_t)h1 << 16);
                    *(uint32_t*)(row + Ndim + cc) = (uint32_t)l0 | ((uint32_t)l1 << 16);
                }
            }
        }
    } else {
        float* Cb = (float*)Cv + (long long)blockIdx.z * sC;
#pragma unroll
        for (int nb = 0; nb < 8; nb++) {
            const int cc = cBase + nb * 8;
            float bx = 0.f, by = 0.f;
            if (HAS_BIAS) { bx = bias[cc]; by = bias[cc + 1]; }
#pragma unroll
            for (int mb = 0; mb < 4; mb++) {
                const int r = rBase + mb * 16;
                float2 v0, v1;
                v0.x = acc[mb][nb][0] + bx; v0.y = acc[mb][nb][1] + by;
                v1.x = acc[mb][nb][2] + bx; v1.y = acc[mb][nb][3] + by;
                *(float2*)(Cb + (long long)r * Ndim + cc)       = v0;
                *(float2*)(Cb + (long long)(r + 8) * Ndim + cc) = v1;
            }
        }
    }
}

// ===========================================================================
// Register-resident causal softmax, emits bf16 hi/lo split planes directly.
// Warp-shuffle reductions: butterfly within warps, 8 partials via smem,
// warp-0 combine, smem broadcast (4 barriers total vs 16 for smem trees).
// parity selects which 128-row tiles this launch handles (q/128 parity).
// ===========================================================================
__global__ __launch_bounds__(256) void softmax_split(
    const float* __restrict__ P, unsigned short* __restrict__ P2, int parity)
{
    using namespace cfg;
    const int idx = blockIdx.x;              // 0 .. B*S/2-1
    const int b   = idx >> 10;               // S/2 = 1024 rows per batch half
    const int r   = idx & 1023;
    const int q   = (((r >> 7) << 1) + parity) * 128 + (r & 127);
    const float* src = P + (long long)b * S * S + (long long)q * S;
    unsigned short* dst = P2 + ((long long)b * S + q) * (2 * S);
    const int len = q + 1;
    const int blockEnd = ((q >> 7) + 1) << 7;
    const int tid  = threadIdx.x;
    const int lane = tid & 31;
    const int wid  = tid >> 5;

    __shared__ float red[8];
    __shared__ float bc;

    float v[8];
#pragma unroll
    for (int j = 0; j < 2; j++) {
        const int i0 = (tid + j * 256) * 4;
        if (i0 < blockEnd) {
            *(float4*)&v[j * 4] = *(const float4*)(src + i0);
        } else {
            v[j * 4] = v[j * 4 + 1] = v[j * 4 + 2] = v[j * 4 + 3] = 0.f;
        }
    }

    // ---- masked max: warp butterfly -> 8 partials -> warp0 -> broadcast ----
    float m = -3.4e38f;
#pragma unroll
    for (int j = 0; j < 2; j++)
#pragma unroll
        for (int t = 0; t < 4; t++) {
            const int i = (tid + j * 256) * 4 + t;
            if (i < len) m = fmaxf(m, v[j * 4 + t]);
        }
#pragma unroll
    for (int o = 16; o > 0; o >>= 1)
        m = fmaxf(m, __shfl_xor_sync(0xFFFFFFFFu, m, o));
    if (lane == 0) red[wid] = m;
    __syncthreads();
    if (wid == 0) {
        float t8 = red[lane & 7];
#pragma unroll
        for (int o = 4; o > 0; o >>= 1)
            t8 = fmaxf(t8, __shfl_xor_sync(0xFFFFFFFFu, t8, o));
        if (lane == 0) bc = t8;
    }
    __syncthreads();
    m = bc;

    // ---- masked exp + sum (registers), same reduction pattern --------------
    float e[8];
    float sum = 0.f;
#pragma unroll
    for (int j = 0; j < 2; j++)
#pragma unroll
        for (int t = 0; t < 4; t++) {
            const int i = (tid + j * 256) * 4 + t;
            const float ev = (i < len) ? __expf(v[j * 4 + t] - m) : 0.f;
            e[j * 4 + t] = ev;
            sum += ev;
        }
#pragma unroll
    for (int o = 16; o > 0; o >>= 1)
        sum += __shfl_xor_sync(0xFFFFFFFFu, sum, o);
    if (lane == 0) red[wid] = sum;
    __syncthreads();
    if (wid == 0) {
        float t8 = red[lane & 7];
#pragma unroll
        for (int o = 4; o > 0; o >>= 1)
            t8 += __shfl_xor_sync(0xFFFFFFFFu, t8, o);
        if (lane == 0) bc = t8;
    }
    __syncthreads();
    const float inv = 1.f / bc;

    // ---- normalize + split-write both planes over [0, blockEnd) -----------
#pragma unroll
    for (int j = 0; j < 2; j++) {
        const int i = (tid + j * 256) * 4;
        if (i < blockEnd) {
            unsigned short h[4], l[4];
#pragma unroll
            for (int t = 0; t < 4; t++) split1(e[j * 4 + t] * inv, h[t], l[t]);
            uint2 hv, lv;
            hv.x = (uint32_t)h[0] | ((uint32_t)h[1] << 16);
            hv.y = (uint32_t)h[2] | ((uint32_t)h[3] << 16);
            lv.x = (uint32_t)l[0] | ((uint32_t)l[1] << 16);
            lv.y = (uint32_t)l[2] | ((uint32_t)l[3] << 16);
            *(uint2*)(dst + i)     = hv;
            *(uint2*)(dst + S + i) = lv;
        }
    }
}

// ---------------- persistent stream/event pool (lazy, one-time) ------------
struct StreamPool {
    cudaStream_t s1, s2;
    cudaEvent_t eFork, eK, eV, eSA, eJ;
    StreamPool() {
        cudaStreamCreateWithFlags(&s1, cudaStreamNonBlocking);
        cudaStreamCreateWithFlags(&s2, cudaStreamNonBlocking);
        cudaEventCreateWithFlags(&eFork, cudaEventDisableTiming);
        cudaEventCreateWithFlags(&eK,    cudaEventDisableTiming);
        cudaEventCreateWithFlags(&eV,    cudaEventDisableTiming);
        cudaEventCreateWithFlags(&eSA,   cudaEventDisableTiming);
        cudaEventCreateWithFlags(&eJ,    cudaEventDisableTiming);
    }
};
static StreamPool& pool() { static StreamPool p; return p; }

// ===========================================================================
// launch — forked-stream capture with parity pipelines (best measured):
//   main: convX, convW -> projQ -> scoresA(odd) -> softmaxA -> PVA(odd)
//   s1:   projK ; then scoresB(even) -> softmaxB -> PVB(even)
//   s2:   projV -> conv V^T
// ===========================================================================
extern "C" void kernel_launch(void* const* d_in, const int* in_sizes, int n_in,
                              void* d_out, int out_size)
{
    using namespace cfg;
    const float* x  = (const float*)d_in[0];
    const float* Wq = (const float*)d_in[1];
    const float* bq = (const float*)d_in[2];
    const float* Wk = (const float*)d_in[3];
    const float* bk = (const float*)d_in[4];
    const float* Wv = (const float*)d_in[5];
    const float* bv = (const float*)d_in[6];
    float* out = (float*)d_out;

    float *v, *p;
    unsigned short *x2, *wq2, *wk2, *wv2, *q2, *k2, *v2t, *p2;
    cudaGetSymbolAddress((void**)&v, g_v);
    cudaGetSymbolAddress((void**)&p, g_p);
    cudaGetSymbolAddress((void**)&x2,  g_x2);
    cudaGetSymbolAddress((void**)&wq2, g_wq2);
    cudaGetSymbolAddress((void**)&wk2, g_wk2);
    cudaGetSymbolAddress((void**)&wv2, g_wv2);
    cudaGetSymbolAddress((void**)&q2,  g_q2);
    cudaGetSymbolAddress((void**)&k2,  g_k2);
    cudaGetSymbolAddress((void**)&v2t, g_v2t);
    cudaGetSymbolAddress((void**)&p2,  g_p2);

    const int SMEM_DYN = 98304;   // 3 stages x (16KB A + 16KB B)
    cudaFuncSetAttribute(mma_gemm<true,  false, false, true>,
                         cudaFuncAttributeMaxDynamicSharedMemorySize, SMEM_DYN);
    cudaFuncSetAttribute(mma_gemm<true,  false, false, false>,
                         cudaFuncAttributeMaxDynamicSharedMemorySize, SMEM_DYN);
    cudaFuncSetAttribute(mma_gemm<false, true,  false, false>,
                         cudaFuncAttributeMaxDynamicSharedMemorySize, SMEM_DYN);
    cudaFuncSetAttribute(mma_gemm<false, false, true,  false>,
                         cudaFuncAttributeMaxDynamicSharedMemorySize, SMEM_DYN);

    StreamPool& sp = pool();   // created on first (correctness) call only

    // ---- main stream: input splits --------------------------------------
    conv_split<<<8192, 256>>>(x, x2, (unsigned)(MR * D / 4), (unsigned)(D / 4), D);
    {
        dim3 g(D / 32, D / 32, 3), b2(32, 8);
        conv_split_T<<<g, b2>>>(Wq, Wk, Wv, wq2, wk2, wv2, D, D, 0, 0, 1);
    }
    cudaEventRecord(sp.eFork, 0);
    cudaStreamWaitEvent(sp.s1, sp.eFork, 0);
    cudaStreamWaitEvent(sp.s2, sp.eFork, 0);

    // ---- projections: Q main, K on s1, V (+transpose) on s2 -------------
    {
        dim3 g(D / 128, MR / 128, 1), b2(128);
        mma_gemm<true, false, false, true ><<<g, b2, SMEM_DYN, 0    >>>(x2, wq2, bq, q2, D, D, 0, 0, 0, 1, 0);
        mma_gemm<true, false, false, true ><<<g, b2, SMEM_DYN, sp.s1>>>(x2, wk2, bk, k2, D, D, 0, 0, 0, 1, 0);
        mma_gemm<true, false, false, false><<<g, b2, SMEM_DYN, sp.s2>>>(x2, wv2, bv, v,  D, D, 0, 0, 0, 1, 0);
    }
    {   // V^T hi/lo per batch, stays on s2
        dim3 g(D / 32, S / 32, B), b2(32, 8);
        conv_split_T<<<g, b2, 0, sp.s2>>>(v, nullptr, nullptr, v2t, nullptr, nullptr,
                                          S, D, (long long)S * D, (long long)D * 2 * S, 0);
    }
    cudaEventRecord(sp.eK, sp.s1);
    cudaEventRecord(sp.eV, sp.s2);

    const long long sAsc = (long long)S * 2 * D, sCsc = (long long)S * S;
    const long long sApv = (long long)S * 2 * S, sBpv = (long long)D * 2 * S;
    const long long sCpv = (long long)S * D;

    // ---- scoresA (odd y-tiles) on main: needs Q (main) and K (s1) --------
    cudaStreamWaitEvent(0, sp.eK, 0);
    {
        dim3 g(S / 128, 8, B), b2(128);
        mma_gemm<false, true, false, false><<<g, b2, SMEM_DYN>>>(
            q2, k2, nullptr, p, S, D, sAsc, sAsc, sCsc, 2, 1);
    }
    cudaEventRecord(sp.eSA, 0);

    // ---- s1: scoresB (even) -> softmaxB -> PVB (even) --------------------
    cudaStreamWaitEvent(sp.s1, sp.eSA, 0);
    {
        dim3 g(S / 128, 8, B), b2(128);
        mma_gemm<false, true, false, false><<<g, b2, SMEM_DYN, sp.s1>>>(
            q2, k2, nullptr, p, S, D, sAsc, sAsc, sCsc, 2, 0);
    }
    softmax_split<<<B * S / 2, 256, 0, sp.s1>>>(p, p2, 0);
    cudaStreamWaitEvent(sp.s1, sp.eV, 0);
    {
        dim3 g(D / 128, 8, B), b2(128);
        mma_gemm<false, false, true, false><<<g, b2, SMEM_DYN, sp.s1>>>(
            p2, v2t, nullptr, out, D, S, sApv, sBpv, sCpv, 2, 0);
    }
    cudaEventRecord(sp.eJ, sp.s1);

    // ---- main: softmaxA (odd) -> PVA (odd) --------------------------------
    softmax_split<<<B * S / 2, 256>>>(p, p2, 1);
    cudaStreamWaitEvent(0, sp.eV, 0);
    {
        dim3 g(D / 128, 8, B), b2(128);
        mma_gemm<false, false, true, false><<<g, b2, SMEM_DYN>>>(
            p2, v2t, nullptr, out, D, S, sApv, sBpv, sCpv, 2, 1);
    }
    cudaStreamWaitEvent(0, sp.eJ, 0);   // join s1 back into main
}

// round 17
// speedup vs baseline: 1.0591x; 1.0009x over previous
#include <cuda_runtime.h>
#include <cuda_bf16.h>
#include <cstdint>

// ===========================================================================
// Causal self-attention via mma.sync bf16 (sm_103 non-'a' compatible).
// All GEMMs: bf16 3-term hi/lo split (fp32-accurate), fp32 accumulate.
// GEMM: CTA tile 128x128, 4 warps (warp tile 64x64), BK=64, 3-stage cp.async
//       (staged mid-chunk), 2 CTAs/SM.
// Schedule (best measured): parity-split scores/softmax/PV pipelines on two
// streams; K-proj on s1, V-proj+V^T on s2; convX/convW serial pre-fork.
// Softmax: warp-shuffle reductions + LPT block order (longest rows first).
// ===========================================================================

namespace cfg {
constexpr int B = 4;
constexpr int S = 2048;
constexpr int D = 1024;
constexpr int MR = B * S;          // 8192
}

// ---------------- scratch (__device__ globals; no allocations) -------------
__device__ float g_v[cfg::MR * cfg::D];
__device__ float g_p[(long long)cfg::B * cfg::S * cfg::S];

// bf16 hi/lo planes, stored as [rows][2K] = [hi(0..K-1) | lo(0..K-1)]
__device__ unsigned short g_x2 [(long long)cfg::MR * 2 * cfg::D];
__device__ unsigned short g_wq2[(long long)cfg::D  * 2 * cfg::D];   // [n][2K], W^T
__device__ unsigned short g_wk2[(long long)cfg::D  * 2 * cfg::D];
__device__ unsigned short g_wv2[(long long)cfg::D  * 2 * cfg::D];
__device__ unsigned short g_q2 [(long long)cfg::MR * 2 * cfg::D];
__device__ unsigned short g_k2 [(long long)cfg::MR * 2 * cfg::D];
__device__ unsigned short g_v2t[(long long)cfg::B * cfg::D * 2 * cfg::S]; // [b][d][2S], V^T
__device__ unsigned short g_p2 [(long long)cfg::B * cfg::S * 2 * cfg::S];

// ---------------- PTX helpers ----------------------------------------------
__device__ __forceinline__ uint32_t smem_u32(const void* p) {
    uint32_t a;
    asm("{ .reg .u64 t; cvta.to.shared.u64 t, %1; cvt.u32.u64 %0, t; }"
        : "=r"(a) : "l"(p));
    return a;
}

#define CP_ASYNC_16(dst, src)                                                 \
    asm volatile("cp.async.cg.shared.global [%0], [%1], 16;"                  \
                 :: "r"(dst), "l"(src))
#define CP_COMMIT() asm volatile("cp.async.commit_group;" ::: "memory")
#define CP_WAIT_1() asm volatile("cp.async.wait_group 1;" ::: "memory")
#define CP_WAIT_0() asm volatile("cp.async.wait_group 0;" ::: "memory")

#define LDSM_X4(r0, r1, r2, r3, addr)                                         \
    asm volatile("ldmatrix.sync.aligned.m8n8.x4.shared.b16 {%0,%1,%2,%3}, [%4];" \
                 : "=r"(r0), "=r"(r1), "=r"(r2), "=r"(r3) : "r"(addr))

#define MMA_BF16(d, a, b)                                                     \
    asm volatile("mma.sync.aligned.m16n8k16.row.col.f32.bf16.bf16.f32 "       \
                 "{%0,%1,%2,%3},{%4,%5,%6,%7},{%8,%9},{%0,%1,%2,%3};"         \
                 : "+f"((d)[0]), "+f"((d)[1]), "+f"((d)[2]), "+f"((d)[3])     \
                 : "r"((a)[0]), "r"((a)[1]), "r"((a)[2]), "r"((a)[3]),        \
                   "r"((b)[0]), "r"((b)[1]))

// ---------------- hi/lo split helper ---------------------------------------
__device__ __forceinline__ void split1(float v, unsigned short& h, unsigned short& l) {
    __nv_bfloat16 hb = __float2bfloat16(v);
    float rem = v - __bfloat162float(hb);
    __nv_bfloat16 lb = __float2bfloat16(rem);
    h = __bfloat16_as_ushort(hb);
    l = __bfloat16_as_ushort(lb);
}

// fp32 [rows][K] -> bf16 [rows][2K] (hi plane | lo plane)
__global__ __launch_bounds__(256) void conv_split(
    const float* __restrict__ in, unsigned short* __restrict__ out,
    unsigned int total4, unsigned int Kq /* = K/4 */, int K)
{
    for (unsigned int i = blockIdx.x * blockDim.x + threadIdx.x; i < total4;
         i += gridDim.x * blockDim.x) {
        unsigned int r = i / Kq;
        unsigned int c4 = i - r * Kq;
        float4 v = *(const float4*)(in + (long long)r * K + c4 * 4);
        unsigned short h0, h1, h2, h3, l0, l1, l2, l3;
        split1(v.x, h0, l0); split1(v.y, h1, l1);
        split1(v.z, h2, l2); split1(v.w, h3, l3);
        uint2 hv, lv;
        hv.x = (uint32_t)h0 | ((uint32_t)h1 << 16);
        hv.y = (uint32_t)h2 | ((uint32_t)h3 << 16);
        lv.x = (uint32_t)l0 | ((uint32_t)l1 << 16);
        lv.y = (uint32_t)l2 | ((uint32_t)l3 << 16);
        unsigned short* orow = out + (long long)r * 2 * K;
        *(uint2*)(orow + c4 * 4)     = hv;
        *(uint2*)(orow + K + c4 * 4) = lv;
    }
}

// fp32 [Krows][Ncols] -> bf16 [Ncols][2*Krows] transposed hi/lo (for W^T, V^T)
// zmode=1: blockIdx.z selects tensor (weights fused); zmode=0: z is batch.
__global__ __launch_bounds__(256) void conv_split_T(
    const float* __restrict__ in0, const float* __restrict__ in1,
    const float* __restrict__ in2,
    unsigned short* __restrict__ out0, unsigned short* __restrict__ out1,
    unsigned short* __restrict__ out2,
    int Krows, int Ncols, long long sIn, long long sOut, int zmode)
{
    __shared__ float t[32][33];
    const float* ib;
    unsigned short* ob;
    if (zmode) {
        ib = (blockIdx.z == 0) ? in0 : (blockIdx.z == 1) ? in1 : in2;
        ob = (blockIdx.z == 0) ? out0 : (blockIdx.z == 1) ? out1 : out2;
    } else {
        ib = in0 + (long long)blockIdx.z * sIn;
        ob = out0 + (long long)blockIdx.z * sOut;
    }
    const int k0 = blockIdx.y * 32, n0 = blockIdx.x * 32;
    const int tx = threadIdx.x, ty = threadIdx.y;     // (32, 8)
#pragma unroll
    for (int i = 0; i < 4; i++)
        t[ty + i * 8][tx] = ib[(long long)(k0 + ty + i * 8) * Ncols + n0 + tx];
    __syncthreads();
    const int ld2 = 2 * Krows;
#pragma unroll
    for (int i = 0; i < 4; i++) {
        int n = n0 + ty + i * 8;
        int k = k0 + tx;
        unsigned short h, l;
        split1(t[tx][ty + i * 8], h, l);
        ob[(long long)n * ld2 + k]         = h;
        ob[(long long)n * ld2 + Krows + k] = l;
    }
}

// ===========================================================================
// mma.sync GEMM: C[m,n] = sum over 3 bf16 term-pairs of A2,B2 (+bias)
//   A2: [M][2K] hi|lo, segments {hi,hi,lo};  B2: [N][2K] hi|lo, segs {hi,lo,hi}
// CTA tile 128x128, 4 warps, warp tile 64x64 (2x2 grid), BK=64, 3-stage,
// next-next chunk staged mid-chunk.
// m-tile index = yIdx*yStride + yBase (parity splits); KBOUND reverses y
// (longest K-loop first) for wave packing; CAUSAL_SKIP drops masked tiles.
// EPI_SPLIT: C is ushort* [M][2N] hi|lo (fused output split for Q/K).
// ===========================================================================
template <bool HAS_BIAS, bool CAUSAL_SKIP, bool KBOUND, bool EPI_SPLIT>
__global__ __launch_bounds__(128, 2) void mma_gemm(
    const unsigned short* __restrict__ A2, const unsigned short* __restrict__ B2,
    const float* __restrict__ bias, void* __restrict__ Cv,
    int Ndim, int Kdim, long long sA, long long sB, long long sC,
    int yStride, int yBase)
{
    const int yIdx = KBOUND ? (gridDim.y - 1 - blockIdx.y) : blockIdx.y;
    const int m0 = (yIdx * yStride + yBase) * 128;
    const int n0 = blockIdx.x * 128;
    if (CAUSAL_SKIP && n0 > m0 + 127) return;

    extern __shared__ char dynsmem[];
    const uint32_t sb = smem_u32(dynsmem);

    const int tid  = threadIdx.x;
    const int lane = tid & 31;
    const int warp = tid >> 5;
    const int wm   = warp >> 1;       // 0..1
    const int wn   = warp & 1;        // 0..1

    const long long ldAe = 2LL * Kdim;            // elements per row
    const long long ldBytes = ldAe * 2;
    const char* baseA = (const char*)(A2 + (long long)blockIdx.z * sA + (long long)m0 * ldAe);
    const char* baseB = (const char*)(B2 + (long long)blockIdx.z * sB + (long long)n0 * ldAe);

    const int segK = KBOUND ? (m0 + 128) : Kdim;
    const int nps = segK >> 6;                    // 64-elem chunks per segment
    const int nChunks = 3 * nps;

    // ---- staging mapping: 128 threads; thread -> (row, 16B unit)
    const int srow = tid >> 3;                    // 0..15
    const int su   = tid & 7;                     // 0..7
    const uint32_t sdst = (uint32_t)(srow * 128 + ((su ^ (srow & 7)) << 4));
    const long long sgoff = (long long)srow * ldBytes + su * 16;

    auto stage = [&](int c, int buf) {
        const int seg = c / nps, kc = c - seg * nps;
        const long long offA = ((long long)kc * 64 + (seg == 2 ? (long long)Kdim : 0)) * 2;
        const long long offB = ((long long)kc * 64 + (seg == 1 ? (long long)Kdim : 0)) * 2;
        const char* ga = baseA + offA + sgoff;
        const char* gb = baseB + offB + sgoff;
        const uint32_t da = sb + buf * 32768u + sdst;
        const uint32_t db = da + 16384u;
#pragma unroll
        for (int i = 0; i < 8; i++) {     // 128 rows each, 16 apart
            CP_ASYNC_16(da + i * 2048u, ga + (long long)i * 16 * ldBytes);
            CP_ASYNC_16(db + i * 2048u, gb + (long long)i * 16 * ldBytes);
        }
        CP_COMMIT();
    };

    float acc[4][8][4];
#pragma unroll
    for (int i = 0; i < 4; i++)
#pragma unroll
        for (int j = 0; j < 8; j++)
#pragma unroll
            for (int t = 0; t < 4; t++) acc[i][j][t] = 0.f;

    // per-lane ldmatrix address components (XOR swizzle: chunk ^= row&7)
    const uint32_t aRowBase = (uint32_t)(wm * 64 + (lane & 15));
    const uint32_t aChunkX  = (uint32_t)(lane >> 4);
    const uint32_t bRowBase = (uint32_t)(wn * 64 + (lane & 7) + ((lane & 16) >> 1));
    const uint32_t bChunkX  = (uint32_t)((lane >> 3) & 1);
    const uint32_t lxor     = (uint32_t)(lane & 7);

    stage(0, 0);
    stage(1, 1);

    for (int c = 0; c < nChunks; c++) {
        if (c + 1 < nChunks) { CP_WAIT_1(); } else { CP_WAIT_0(); }
        __syncthreads();

        const uint32_t sAb = sb + (uint32_t)(c % 3) * 32768u;
        const uint32_t sBb = sAb + 16384u;

        auto compute_s = [&](int s) {
            uint32_t a[4][4];
            uint32_t b[4][4];          // [nb2][{b0lo,b0hi,b1lo,b1hi}]
#pragma unroll
            for (int mb = 0; mb < 4; mb++) {
                const uint32_t addr = sAb + (aRowBase + mb * 16) * 128u
                                    + (((s * 2 + aChunkX) ^ lxor) << 4);
                LDSM_X4(a[mb][0], a[mb][1], a[mb][2], a[mb][3], addr);
            }
#pragma unroll
            for (int nb2 = 0; nb2 < 4; nb2++) {
                const uint32_t addr = sBb + (bRowBase + nb2 * 16) * 128u
                                    + (((s * 2 + bChunkX) ^ lxor) << 4);
                LDSM_X4(b[nb2][0], b[nb2][1], b[nb2][2], b[nb2][3], addr);
            }
#pragma unroll
            for (int nb2 = 0; nb2 < 4; nb2++)
#pragma unroll
                for (int mb = 0; mb < 4; mb++) {
                    MMA_BF16(acc[mb][nb2 * 2],     a[mb], &b[nb2][0]);
                    MMA_BF16(acc[mb][nb2 * 2 + 1], a[mb], &b[nb2][2]);
                }
        };

        compute_s(0);
        compute_s(1);
        if (c + 2 < nChunks) stage(c + 2, (c + 2) % 3);  // mid-chunk prefetch
        compute_s(2);
        compute_s(3);
    }

    // ---- epilogue ----------------------------------------------------------
    const int rBase = m0 + wm * 64 + (lane >> 2);
    const int cBase = n0 + wn * 64 + (lane & 3) * 2;

    if (EPI_SPLIT) {
        unsigned short* Cs = (unsigned short*)Cv + (long long)blockIdx.z * sC;
#pragma unroll
        for (int nb = 0; nb < 8; nb++) {
            const int cc = cBase + nb * 8;
            float bx = 0.f, by = 0.f;
            if (HAS_BIAS) { bx = bias[cc]; by = bias[cc + 1]; }
#pragma unroll
            for (int mb = 0; mb < 4; mb++) {
                const int r = rBase + mb * 16;
#pragma unroll
                for (int half = 0; half < 2; half++) {
                    const float v0 = acc[mb][nb][half * 2]     + bx;
                    const float v1 = acc[mb][nb][half * 2 + 1] + by;
                    unsigned short h0, l0, h1, l1;
                    split1(v0, h0, l0);
                    split1(v1, h1, l1);
                    unsigned short* row = Cs + (long long)(r + half * 8) * (2 * Ndim);
                    *(uint32_t*)(row + cc)        = (uint32_t)h0 | ((uint32_t)h1 << 16);
                    *(uint32_t*)(row + Ndim + cc) = (uint32_t)l0 | ((uint32_t)l1 << 16);
                }
            }
        }
    } else {
        float* Cb = (float*)Cv + (long long)blockIdx.z * sC;
#pragma unroll
        for (int nb = 0; nb < 8; nb++) {
            const int cc = cBase + nb * 8;
            float bx = 0.f, by = 0.f;
            if (HAS_BIAS) { bx = bias[cc]; by = bias[cc + 1]; }
#pragma unroll
            for (int mb = 0; mb < 4; mb++) {
                const int r = rBase + mb * 16;
                float2 v0, v1;
                v0.x = acc[mb][nb][0] + bx; v0.y = acc[mb][nb][1] + by;
                v1.x = acc[mb][nb][2] + bx; v1.y = acc[mb][nb][3] + by;
                *(float2*)(Cb + (long long)r * Ndim + cc)       = v0;
                *(float2*)(Cb + (long long)(r + 8) * Ndim + cc) = v1;
            }
        }
    }
}

// ===========================================================================
// Register-resident causal softmax, emits bf16 hi/lo split planes directly.
// Warp-shuffle reductions (4 barriers). LPT order: tile index reversed within
// each batch so longest rows launch first (per-row math unchanged -> output
// bitwise identical).
// parity selects which 128-row tiles this launch handles (q/128 parity).
// ===========================================================================
__global__ __launch_bounds__(256) void softmax_split(
    const float* __restrict__ P, unsigned short* __restrict__ P2, int parity)
{
    using namespace cfg;
    const int idx = blockIdx.x;              // 0 .. B*S/2-1
    const int b   = idx >> 10;               // S/2 = 1024 rows per batch half
    const int r   = idx & 1023;
    const int tile = 7 - (r >> 7);           // LPT: longest rows first
    const int q   = (tile * 2 + parity) * 128 + (r & 127);
    const float* src = P + (long long)b * S * S + (long long)q * S;
    unsigned short* dst = P2 + ((long long)b * S + q) * (2 * S);
    const int len = q + 1;
    const int blockEnd = ((q >> 7) + 1) << 7;
    const int tid  = threadIdx.x;
    const int lane = tid & 31;
    const int wid  = tid >> 5;

    __shared__ float red[8];
    __shared__ float bc;

    float v[8];
#pragma unroll
    for (int j = 0; j < 2; j++) {
        const int i0 = (tid + j * 256) * 4;
        if (i0 < blockEnd) {
            *(float4*)&v[j * 4] = *(const float4*)(src + i0);
        } else {
            v[j * 4] = v[j * 4 + 1] = v[j * 4 + 2] = v[j * 4 + 3] = 0.f;
        }
    }

    // ---- masked max: warp butterfly -> 8 partials -> warp0 -> broadcast ----
    float m = -3.4e38f;
#pragma unroll
    for (int j = 0; j < 2; j++)
#pragma unroll
        for (int t = 0; t < 4; t++) {
            const int i = (tid + j * 256) * 4 + t;
            if (i < len) m = fmaxf(m, v[j * 4 + t]);
        }
#pragma unroll
    for (int o = 16; o > 0; o >>= 1)
        m = fmaxf(m, __shfl_xor_sync(0xFFFFFFFFu, m, o));
    if (lane == 0) red[wid] = m;
    __syncthreads();
    if (wid == 0) {
        float t8 = red[lane & 7];
#pragma unroll
        for (int o = 4; o > 0; o >>= 1)
            t8 = fmaxf(t8, __shfl_xor_sync(0xFFFFFFFFu, t8, o));
        if (lane == 0) bc = t8;
    }
    __syncthreads();
    m = bc;

    // ---- masked exp + sum (registers), same reduction pattern --------------
    float e[8];
    float sum = 0.f;
#pragma unroll
    for (int j = 0; j < 2; j++)
#pragma unroll
        for (int t = 0; t < 4; t++) {
            const int i = (tid + j * 256) * 4 + t;
            const float ev = (i < len) ? __expf(v[j * 4 + t] - m) : 0.f;
            e[j * 4 + t] = ev;
            sum += ev;
        }
#pragma unroll
    for (int o = 16; o > 0; o >>= 1)
        sum += __shfl_xor_sync(0xFFFFFFFFu, sum, o);
    if (lane == 0) red[wid] = sum;
    __syncthreads();
    if (wid == 0) {
        float t8 = red[lane & 7];
#pragma unroll
        for (int o = 4; o > 0; o >>= 1)
            t8 += __shfl_xor_sync(0xFFFFFFFFu, t8, o);
        if (lane == 0) bc = t8;
    }
    __syncthreads();
    const float inv = 1.f / bc;

    // ---- normalize + split-write both planes over [0, blockEnd) -----------
#pragma unroll
    for (int j = 0; j < 2; j++) {
        const int i = (tid + j * 256) * 4;
        if (i < blockEnd) {
            unsigned short h[4], l[4];
#pragma unroll
            for (int t = 0; t < 4; t++) split1(e[j * 4 + t] * inv, h[t], l[t]);
            uint2 hv, lv;
            hv.x = (uint32_t)h[0] | ((uint32_t)h[1] << 16);
            hv.y = (uint32_t)h[2] | ((uint32_t)h[3] << 16);
            lv.x = (uint32_t)l[0] | ((uint32_t)l[1] << 16);
            lv.y = (uint32_t)l[2] | ((uint32_t)l[3] << 16);
            *(uint2*)(dst + i)     = hv;
            *(uint2*)(dst + S + i) = lv;
        }
    }
}

// ---------------- persistent stream/event pool (lazy, one-time) ------------
struct StreamPool {
    cudaStream_t s1, s2;
    cudaEvent_t eFork, eK, eV, eSA, eJ;
    StreamPool() {
        cudaStreamCreateWithFlags(&s1, cudaStreamNonBlocking);
        cudaStreamCreateWithFlags(&s2, cudaStreamNonBlocking);
        cudaEventCreateWithFlags(&eFork, cudaEventDisableTiming);
        cudaEventCreateWithFlags(&eK,    cudaEventDisableTiming);
        cudaEventCreateWithFlags(&eV,    cudaEventDisableTiming);
        cudaEventCreateWithFlags(&eSA,   cudaEventDisableTiming);
        cudaEventCreateWithFlags(&eJ,    cudaEventDisableTiming);
    }
};
static StreamPool& pool() { static StreamPool p; return p; }

// ===========================================================================
// launch — forked-stream capture with parity pipelines (best measured):
//   main: convX, convW -> projQ -> scoresA(odd) -> softmaxA -> PVA(odd)
//   s1:   projK ; then scoresB(even) -> softmaxB -> PVB(even)
//   s2:   projV -> conv V^T
// ===========================================================================
extern "C" void kernel_launch(void* const* d_in, const int* in_sizes, int n_in,
                              void* d_out, int out_size)
{
    using namespace cfg;
    const float* x  = (const float*)d_in[0];
    const float* Wq = (const float*)d_in[1];
    const float* bq = (const float*)d_in[2];
    const float* Wk = (const float*)d_in[3];
    const float* bk = (const float*)d_in[4];
    const float* Wv = (const float*)d_in[5];
    const float* bv = (const float*)d_in[6];
    float* out = (float*)d_out;

    float *v, *p;
    unsigned short *x2, *wq2, *wk2, *wv2, *q2, *k2, *v2t, *p2;
    cudaGetSymbolAddress((void**)&v, g_v);
    cudaGetSymbolAddress((void**)&p, g_p);
    cudaGetSymbolAddress((void**)&x2,  g_x2);
    cudaGetSymbolAddress((void**)&wq2, g_wq2);
    cudaGetSymbolAddress((void**)&wk2, g_wk2);
    cudaGetSymbolAddress((void**)&wv2, g_wv2);
    cudaGetSymbolAddress((void**)&q2,  g_q2);
    cudaGetSymbolAddress((void**)&k2,  g_k2);
    cudaGetSymbolAddress((void**)&v2t, g_v2t);
    cudaGetSymbolAddress((void**)&p2,  g_p2);

    const int SMEM_DYN = 98304;   // 3 stages x (16KB A + 16KB B)
    cudaFuncSetAttribute(mma_gemm<true,  false, false, true>,
                         cudaFuncAttributeMaxDynamicSharedMemorySize, SMEM_DYN);
    cudaFuncSetAttribute(mma_gemm<true,  false, false, false>,
                         cudaFuncAttributeMaxDynamicSharedMemorySize, SMEM_DYN);
    cudaFuncSetAttribute(mma_gemm<false, true,  false, false>,
                         cudaFuncAttributeMaxDynamicSharedMemorySize, SMEM_DYN);
    cudaFuncSetAttribute(mma_gemm<false, false, true,  false>,
                         cudaFuncAttributeMaxDynamicSharedMemorySize, SMEM_DYN);

    StreamPool& sp = pool();   // created on first (correctness) call only

    // ---- main stream: input splits --------------------------------------
    conv_split<<<8192, 256>>>(x, x2, (unsigned)(MR * D / 4), (unsigned)(D / 4), D);
    {
        dim3 g(D / 32, D / 32, 3), b2(32, 8);
        conv_split_T<<<g, b2>>>(Wq, Wk, Wv, wq2, wk2, wv2, D, D, 0, 0, 1);
    }
    cudaEventRecord(sp.eFork, 0);
    cudaStreamWaitEvent(sp.s1, sp.eFork, 0);
    cudaStreamWaitEvent(sp.s2, sp.eFork, 0);

    // ---- projections: Q main, K on s1, V (+transpose) on s2 -------------
    {
        dim3 g(D / 128, MR / 128, 1), b2(128);
        mma_gemm<true, false, false, true ><<<g, b2, SMEM_DYN, 0    >>>(x2, wq2, bq, q2, D, D, 0, 0, 0, 1, 0);
        mma_gemm<true, false, false, true ><<<g, b2, SMEM_DYN, sp.s1>>>(x2, wk2, bk, k2, D, D, 0, 0, 0, 1, 0);
        mma_gemm<true, false, false, false><<<g, b2, SMEM_DYN, sp.s2>>>(x2, wv2, bv, v,  D, D, 0, 0, 0, 1, 0);
    }
    {   // V^T hi/lo per batch, stays on s2
        dim3 g(D / 32, S / 32, B), b2(32, 8);
        conv_split_T<<<g, b2, 0, sp.s2>>>(v, nullptr, nullptr, v2t, nullptr, nullptr,
                                          S, D, (long long)S * D, (long long)D * 2 * S, 0);
    }
    cudaEventRecord(sp.eK, sp.s1);
    cudaEventRecord(sp.eV, sp.s2);

    const long long sAsc = (long long)S * 2 * D, sCsc = (long long)S * S;
    const long long sApv = (long long)S * 2 * S, sBpv = (long long)D * 2 * S;
    const long long sCpv = (long long)S * D;

    // ---- scoresA (odd y-tiles) on main: needs Q (main) and K (s1) --------
    cudaStreamWaitEvent(0, sp.eK, 0);
    {
        dim3 g(S / 128, 8, B), b2(128);
        mma_gemm<false, true, false, false><<<g, b2, SMEM_DYN>>>(
            q2, k2, nullptr, p, S, D, sAsc, sAsc, sCsc, 2, 1);
    }
    cudaEventRecord(sp.eSA, 0);

    // ---- s1: scoresB (even) -> softmaxB -> PVB (even) --------------------
    cudaStreamWaitEvent(sp.s1, sp.eSA, 0);
    {
        dim3 g(S / 128, 8, B), b2(128);
        mma_gemm<false, true, false, false><<<g, b2, SMEM_DYN, sp.s1>>>(
            q2, k2, nullptr, p, S, D, sAsc, sAsc, sCsc, 2, 0);
    }
    softmax_split<<<B * S / 2, 256, 0, sp.s1>>>(p, p2, 0);
    cudaStreamWaitEvent(sp.s1, sp.eV, 0);
    {
        dim3 g(D / 128, 8, B), b2(128);
        mma_gemm<false, false, true, false><<<g, b2, SMEM_DYN, sp.s1>>>(
            p2, v2t, nullptr, out, D, S, sApv, sBpv, sCpv, 2, 0);
    }
    cudaEventRecord(sp.eJ, sp.s1);

    // ---- main: softmaxA (odd) -> PVA (odd) --------------------------------
    softmax_split<<<B * S / 2, 256>>>(p, p2, 1);
    cudaStreamWaitEvent(0, sp.eV, 0);
    {
        dim3 g(D / 128, 8, B), b2(128);
        mma_gemm<false, false, true, false><<<g, b2, SMEM_DYN>>>(
            p2, v2t, nullptr, out, D, S, sApv, sBpv, sCpv, 2, 1);
    }
    cudaStreamWaitEvent(0, sp.eJ, 0);   // join s1 back into main
}